// round 13
// baseline (speedup 1.0000x reference)
#include <cuda_runtime.h>
#include <cuda_fp16.h>
#include <math.h>
#include <stdint.h>

#define NN 25000
#define NE 500000
#define BQ 4
#define DD 32
#define RR 474
#define NL 4
#define KD 416          // 13*D
#define NSTEP 26        // KD/16 k-steps
#define EPSF 1e-6f
#define NPB 8           // nodes per mlp inner batch
#define MLP_IT 8        // batches per mlp block
#define SCAN_B 25       // ceil(25000/1024)

// setup_kernel block partition
#define SB_RELIN (NL * RR)                 // 1896
#define SB_WSPLIT (SB_RELIN + NL * NSTEP)  // +104
#define SB_ZERO (SB_WSPLIT + 25)           // +25 (zero cnt/deg/flags)
#define SB_TOTAL (SB_ZERO + 1)             // +1 (init)

typedef unsigned long long ull;

// ---- packed fp32x2 helpers ----
__device__ __forceinline__ ull fma2(ull a, ull b, ull c) {
    ull d; asm("fma.rn.f32x2 %0,%1,%2,%3;" : "=l"(d) : "l"(a), "l"(b), "l"(c)); return d;
}
__device__ __forceinline__ ull add2(ull a, ull b) {
    ull d; asm("add.rn.f32x2 %0,%1,%2;" : "=l"(d) : "l"(a), "l"(b)); return d;
}
__device__ __forceinline__ ull pk2(float x, float y) {
    ull r; asm("mov.b64 %0,{%1,%2};" : "=l"(r) : "f"(x), "f"(y)); return r;
}
__device__ __forceinline__ ull dup2(float x) {
    ull r; asm("mov.b64 %0,{%1,%1};" : "=l"(r) : "f"(x)); return r;
}
__device__ __forceinline__ float2 unpk(ull a) {
    float2 f; asm("mov.b64 {%0,%1},%2;" : "=f"(f.x), "=f"(f.y) : "l"(a)); return f;
}
__device__ __forceinline__ ull h2f2(__half2 h) {
    const float2 f = __half22float2(h);
    return pk2(f.x, f.y);
}
__device__ __forceinline__ __half2 u2h(uint32_t u) { return *(const __half2*)&u; }
__device__ __forceinline__ uint32_t h2u(__half2 h) { return *(const uint32_t*)&h; }
__device__ __forceinline__ float4 cvt_rv(const uint2 rh) {
    const float2 f01 = __half22float2(u2h(rh.x));
    const float2 f23 = __half22float2(u2h(rh.y));
    return make_float4(f01.x, f01.y, f23.x, f23.y);
}

// split (x0,x1) into bf16 hi pair + bf16 lo pair (lo = x - float(hi))
__device__ __forceinline__ void split2(float x0, float x1, uint32_t& h, uint32_t& l) {
    uint32_t hp; asm("cvt.rn.bf16x2.f32 %0,%1,%2;" : "=r"(hp) : "f"(x1), "f"(x0));
    const float l0 = x0 - __int_as_float(hp << 16);
    const float l1 = x1 - __int_as_float(hp & 0xFFFF0000u);
    uint32_t lp; asm("cvt.rn.bf16x2.f32 %0,%1,%2;" : "=r"(lp) : "f"(l1), "f"(l0));
    h = hp; l = lp;
}

__device__ __forceinline__ void mma16816(float& d0, float& d1, float& d2, float& d3,
                                         uint32_t a0, uint32_t a1, uint32_t a2, uint32_t a3,
                                         uint32_t b0, uint32_t b1) {
    asm volatile("mma.sync.aligned.m16n8k16.row.col.f32.bf16.bf16.f32 "
                 "{%0,%1,%2,%3},{%4,%5,%6,%7},{%8,%9},{%0,%1,%2,%3};"
                 : "+f"(d0), "+f"(d1), "+f"(d2), "+f"(d3)
                 : "r"(a0), "r"(a1), "r"(a2), "r"(a3), "r"(b0), "r"(b1));
}

// ---------------- scratch ----------------
__device__ int    g_cnt[NN];
__device__ float  g_deg[NN];
__device__ int    g_rowptr[NN + 1];
__device__ int    g_pos[NN];
__device__ int2   g_epack[NE];          // CSR-ordered (nin | rel<<16, w_bits)
__device__ float2 g_sc[NN];             // (s1, s2)
__device__ int    g_flag[SCAN_B];
__device__ int    g_partI[SCAN_B];
__device__ float  g_partF[SCAN_B];
__device__ uint2  g_h16A[NN * DD];      // fp16x2 hidden state
__device__ uint2  g_h16B[NN * DD];
__device__ uint2  g_relinH[NL * RR * DD]; // fp16x2 pairs: (b0,b1),(b2,b3)
__device__ float4 g_qT[DD];             // [d] -> b-vector
__device__ float  g_csum[3 * DD];       // layer-0 std-column sums per scale
__device__ uint4  g_Wmma[NL * NSTEP * 128]; // fragment-ordered split weights

// ---------------- fused setup (input-only work, launch #0) ----------------
__global__ void __launch_bounds__(128) setup_kernel(
    const int* __restrict__ h_index,
    const int* __restrict__ r_index,
    const float* __restrict__ query_embed,
    const float* __restrict__ lin_W,
    const float* __restrict__ rel_W,
    const float* __restrict__ rel_b)
{
    const int bx = blockIdx.x;
    const int t = threadIdx.x;

    if (bx < SB_RELIN) {
        __shared__ float acc_s[BQ][DD];
        const int l = bx / RR, r = bx - l * RR;
        const int d = t & 31, b = t >> 5;
        const int ri = __ldg(&r_index[b]);
        const float* W = rel_W + (size_t)l * DD * RR * DD + (size_t)r * DD + d;
        float acc = rel_b[(size_t)l * RR * DD + r * DD + d];
#pragma unroll
        for (int k = 0; k < DD; ++k)
            acc += __ldg(&query_embed[ri * DD + k]) * W[(size_t)k * RR * DD];
        acc_s[b][d] = acc;
        __syncthreads();
        if (t < DD) {
            const __half2 p01 = __floats2half2_rn(acc_s[0][t], acc_s[1][t]);
            const __half2 p23 = __floats2half2_rn(acc_s[2][t], acc_s[3][t]);
            uint2 o;
            o.x = h2u(p01);
            o.y = h2u(p23);
            g_relinH[(size_t)(l * RR + r) * DD + t] = o;
        }
    } else if (bx < SB_WSPLIT) {
        const int i = bx - SB_RELIN;
        const int l = i / NSTEP, s = i % NSTEP;
        const int w = t >> 5, lane = t & 31;
        const int c = lane & 3, n = 8 * w + (lane >> 2);
        const int k0 = 16 * s;
        const float* W = lin_W + (size_t)l * KD * DD;
        const float w00 = W[(k0 + 2 * c) * DD + n];
        const float w01 = W[(k0 + 2 * c + 1) * DD + n];
        const float w10 = W[(k0 + 8 + 2 * c) * DD + n];
        const float w11 = W[(k0 + 9 + 2 * c) * DD + n];
        uint32_t h0, l0, h1, l1;
        split2(w00, w01, h0, l0);
        split2(w10, w11, h1, l1);
        g_Wmma[(size_t)(l * NSTEP + s) * 128 + t] = make_uint4(h0, h1, l0, l1);
    } else if (bx < SB_ZERO) {
        const int bi = bx - SB_WSPLIT;
        const int base = bi * 1000;
        for (int i = base + t; i < base + 1000 && i < NN; i += 128) {
            g_cnt[i] = 0;
            g_deg[i] = 0.0f;
        }
        if (bi == 0 && t < SCAN_B) g_flag[t] = 0;
    } else {
        if (t < 128) {
            const int b = t >> 5, d = t & 31;
            ((float*)g_qT)[d * 4 + b] = __ldg(&query_embed[__ldg(&r_index[b]) * DD + d]);
        }
        __syncthreads();
        if (t < DD) {
            const int j = t;
#pragma unroll
            for (int s = 0; s < 3; ++s) {
                float c = 0.0f;
#pragma unroll
                for (int dd = 0; dd < DD; ++dd)
                    c += lin_W[(DD + (4 * dd + 3) * 3 + s) * DD + j];
                g_csum[s * DD + j] = c;
            }
        }
    }
}

// ---------------- graph-build kernels ----------------
__global__ void hist_kernel(const int* __restrict__ node_out,
                            const float* __restrict__ ew) {
    const int e = blockIdx.x * 256 + threadIdx.x;
    if (e < NE) {
        const int v = node_out[e];
        atomicAdd(&g_cnt[v], 1);
        atomicAdd(&g_deg[v], ew[e]);
    }
}

// single-kernel decoupled scan: local scan + publish partial + poll all flags
__global__ void __launch_bounds__(1024) scan_kernel() {
    __shared__ int wsum[32];
    __shared__ int woff[32];
    __shared__ float lsum[32];
    __shared__ int sI[SCAN_B];
    __shared__ float sF[SCAN_B];
    const int t = threadIdx.x, wid = t >> 5, lane = t & 31;
    const int b = blockIdx.x;
    const int i = b * 1024 + t;
    const int x = (i < NN) ? g_cnt[i] : 0;
    float y = (i < NN) ? logf(g_deg[i] + 1.0f) : 0.0f;

    int incl = x;
#pragma unroll
    for (int off = 1; off < 32; off <<= 1) {
        int n = __shfl_up_sync(0xffffffffu, incl, off);
        if (lane >= off) incl += n;
    }
#pragma unroll
    for (int off = 16; off > 0; off >>= 1)
        y += __shfl_down_sync(0xffffffffu, y, off);
    if (lane == 31) wsum[wid] = incl;
    if (lane == 0)  lsum[wid] = y;
    __syncthreads();
    if (wid == 0) {
        int s = wsum[lane];
        int si = s;
#pragma unroll
        for (int off = 1; off < 32; off <<= 1) {
            int n = __shfl_up_sync(0xffffffffu, si, off);
            if (lane >= off) si += n;
        }
        woff[lane] = si - s;
        float ls = lsum[lane];
#pragma unroll
        for (int off = 16; off > 0; off >>= 1)
            ls += __shfl_down_sync(0xffffffffu, ls, off);
        if (lane == 31) {
            // publish partials, then flag (release)
            g_partI[b] = si;
            g_partF[b] = ls;   // ls only valid in lane 0... fix below
        }
    }
    __syncthreads();
    // fix: lane0 of warp0 holds float total; republish correctly
    if (t == 0) {
        float ftot = 0.0f;
#pragma unroll
        for (int ww = 0; ww < 32; ++ww) ftot += lsum[ww];
        g_partF[b] = ftot;
        __threadfence();
        atomicExch(&g_flag[b], 1);
    }
    // poll all partials
    if (t < SCAN_B) {
        while (atomicAdd(&g_flag[t], 0) == 0) {}
        sI[t] = g_partI[t];
        sF[t] = g_partF[t];
    }
    __syncthreads();
    int off = 0;
    float gl = 0.0f;
#pragma unroll
    for (int j = 0; j < SCAN_B; ++j) {
        if (j < b) off += sI[j];
        gl += sF[j];
    }
    if (i < NN) {
        const int rp = incl - x + woff[wid] + off;
        g_rowptr[i] = rp;
        g_pos[i] = rp;
        const float mean = gl / (float)NN;
        const float s = logf(g_deg[i] + 1.0f) / mean;
        g_sc[i] = make_float2(s, 1.0f / fmaxf(s, 0.01f));
    }
    if (i == 0) g_rowptr[NN] = NE;
}

__global__ void scatter_kernel(const int* __restrict__ node_in,
                               const int* __restrict__ node_out,
                               const int* __restrict__ relation,
                               const float* __restrict__ ew) {
    const int e = blockIdx.x * 256 + threadIdx.x;
    if (e < NE) {
        const int p = atomicAdd(&g_pos[node_out[e]], 1);
        g_epack[p] = make_int2(node_in[e] | (relation[e] << 16),
                               __float_as_int(ew[e]));
    }
}

// ---------------- fused conv layer: 2 warps per node ----------------
__device__ __forceinline__ uint2 ldcg2u(const uint2* p) {
    uint2 v;
    asm volatile("ld.global.cg.v2.u32 {%0,%1},[%2];"
                 : "=r"(v.x), "=r"(v.y) : "l"(p));
    return v;
}

#define WRITE_PAIR(p, x0, x1)                                              \
    do {                                                                   \
        uint32_t hh_, ll_;                                                 \
        split2((x0).x, (x1).x, hh_, ll_);                                  \
        catH[p][r0] = hh_; catL[p][r0] = ll_;                              \
        split2((x0).y, (x1).y, hh_, ll_);                                  \
        catH[p][r0 + 1] = hh_; catL[p][r0 + 1] = ll_;                      \
        split2((x0).z, (x1).z, hh_, ll_);                                  \
        catH[p][r0 + 2] = hh_; catL[p][r0 + 2] = ll_;                      \
        split2((x0).w, (x1).w, hh_, ll_);                                  \
        catH[p][r0 + 3] = hh_; catL[p][r0 + 3] = ll_;                      \
    } while (0)

#define EDGE_CORE(rv_, hh_, wbits_, mw01o, mw23o)                          \
    do {                                                                   \
        const __half2 wh_ = __float2half2_rn(__int_as_float(wbits_));      \
        const __half2 m01_ = __hmul2(u2h((rv_).x), u2h((hh_).x));          \
        const __half2 m23_ = __hmul2(u2h((rv_).y), u2h((hh_).y));          \
        mw01o = __hmul2(m01_, wh_);                                        \
        mw23o = __hmul2(m23_, wh_);                                        \
        mxh01 = __hmax2(mxh01, mw01o); mxh23 = __hmax2(mxh23, mw23o);      \
        mnh01 = __hmin2(mnh01, mw01o); mnh23 = __hmin2(mnh23, mw23o);      \
        sqh01 = __hfma2(m01_, mw01o, sqh01);                               \
        sqh23 = __hfma2(m23_, mw23o, sqh23);                               \
    } while (0)

__global__ void __launch_bounds__(256) conv_kernel(
    const float* __restrict__ lin_b,
    const uint2* __restrict__ h16_in, uint2* __restrict__ h16_out,
    const int* __restrict__ h_index, int layer)
{
    __shared__ uint32_t catH[KD / 2][17];   // 14.1KB
    __shared__ uint32_t catL[KD / 2][17];   // 14.1KB (sD aliases post-GEMM)
    __shared__ ull   mgS[4][32][2];         // half1 partial sums (f32x2), 2KB
    __shared__ uint2 sqS[4][32];            // half1 partial sq (half2), 1KB
    __shared__ uint2 mxS[4][32];
    __shared__ uint2 mnS[4][32];
    __shared__ int s_act[4];
    __shared__ float2 s_scl[4];
    float* sD = (float*)catL;

    const int t = threadIdx.x, w = t >> 5, lane = t & 31;
    const int s = w >> 1, half = w & 1;
    const int v = blockIdx.x * 4 + s;
    const int d = lane;
    const uint2* relin = g_relinH + (size_t)layer * RR * DD + d;

    // ---- message phase (warp pair per node; edge range split) ----
    {
        const int4 h = *(const int4*)h_index;
        const float4 q = g_qT[d];
        const float4 m0 = make_float4(v == h.x ? q.x : 0.f,
                                      v == h.y ? q.y : 0.f,
                                      v == h.z ? q.z : 0.f,
                                      v == h.w ? q.w : 0.f);
        const int lo = g_rowptr[v];
        const int hi = g_rowptr[v + 1];
        const int degv = hi - lo;
        const int mid = lo + ((degv + 1) >> 1);
        int act = 1;
        float4 hv = make_float4(0.f, 0.f, 0.f, 0.f);
        float4 sumF, sqF, mxF, mnF;
        bool have_stats = false;

        if (layer == 0) {
            // half0 warp handles the whole node (cheap select-based path)
            if (half == 0) {
                hv = m0;
                float4 sum = m0, mx = m0, mn = m0;
                float4 sq = make_float4(m0.x * m0.x, m0.y * m0.y, m0.z * m0.z, m0.w * m0.w);
                act = (v == h.x) | (v == h.y) | (v == h.z) | (v == h.w);
                int nacc = 0;
                for (int p = lo; p < hi; ++p) {
                    const int2 ep = __ldg(&g_epack[p]);
                    const int nin = ep.x & 0xFFFF;
                    if (nin == h.x || nin == h.y || nin == h.z || nin == h.w) {
                        act = 1; ++nacc;
                        const uint2 rvh = __ldg(&relin[(ep.x >> 16) * DD]);
                        const float2 r01 = __half22float2(u2h(rvh.x));
                        const float2 r23 = __half22float2(u2h(rvh.y));
                        const float4 hh = make_float4(nin == h.x ? q.x : 0.f,
                                                      nin == h.y ? q.y : 0.f,
                                                      nin == h.z ? q.z : 0.f,
                                                      nin == h.w ? q.w : 0.f);
                        const float wgt = __int_as_float(ep.y);
                        float m, mw;
                        m = r01.x * hh.x; mw = m * wgt; sum.x += mw; sq.x = fmaf(m, mw, sq.x); mx.x = fmaxf(mx.x, mw); mn.x = fminf(mn.x, mw);
                        m = r01.y * hh.y; mw = m * wgt; sum.y += mw; sq.y = fmaf(m, mw, sq.y); mx.y = fmaxf(mx.y, mw); mn.y = fminf(mn.y, mw);
                        m = r23.x * hh.z; mw = m * wgt; sum.z += mw; sq.z = fmaf(m, mw, sq.z); mx.z = fmaxf(mx.z, mw); mn.z = fminf(mn.z, mw);
                        m = r23.y * hh.w; mw = m * wgt; sum.w += mw; sq.w = fmaf(m, mw, sq.w); mx.w = fmaxf(mx.w, mw); mn.w = fminf(mn.w, mw);
                    }
                }
                if (nacc < degv) {
                    mx.x = fmaxf(mx.x, 0.f); mx.y = fmaxf(mx.y, 0.f); mx.z = fmaxf(mx.z, 0.f); mx.w = fmaxf(mx.w, 0.f);
                    mn.x = fminf(mn.x, 0.f); mn.y = fminf(mn.y, 0.f); mn.z = fminf(mn.z, 0.f); mn.w = fminf(mn.w, 0.f);
                }
                sumF = sum; sqF = sq; mxF = mx; mnF = mn;
                have_stats = (act != 0);
            } else {
                act = 0;  // odd warps idle at layer 0 (not used for s_act)
            }
        } else {
            // split range: half0 [lo,mid), half1 [mid,hi)
            int p  = half ? mid : lo;
            const int e_ = half ? hi : mid;
            ull sum01, sum23;
            __half2 sqh01, sqh23, mxh01, mxh23, mnh01, mnh23;
            if (half == 0) {
                hv = cvt_rv(__ldg(&h16_in[v * DD + d]));
                sum01 = pk2(m0.x, m0.y); sum23 = pk2(m0.z, m0.w);
                sqh01 = __floats2half2_rn(m0.x * m0.x, m0.y * m0.y);
                sqh23 = __floats2half2_rn(m0.z * m0.z, m0.w * m0.w);
                mxh01 = __floats2half2_rn(m0.x, m0.y);
                mxh23 = __floats2half2_rn(m0.z, m0.w);
                mnh01 = mxh01; mnh23 = mxh23;
            } else {
                sum01 = 0; sum23 = 0;
                sqh01 = u2h(0u); sqh23 = u2h(0u);
                mxh01 = u2h(0xFC00FC00u); mxh23 = u2h(0xFC00FC00u);  // -inf
                mnh01 = u2h(0x7C007C00u); mnh23 = u2h(0x7C007C00u);  // +inf
            }

            const int nfull = (e_ - p) >> 2;
            if (nfull > 0) {
                int2 ee[4];
#pragma unroll
                for (int j = 0; j < 4; ++j) ee[j] = __ldg(&g_epack[p + j]);
                for (int b = 0; b < nfull; ++b) {
                    uint2 rv[4], hh[4];
#pragma unroll
                    for (int j = 0; j < 4; ++j) {
                        rv[j] = __ldg(&relin[(ee[j].x >> 16) * DD]);
                        hh[j] = ldcg2u(&h16_in[(ee[j].x & 0xFFFF) * DD + d]);
                    }
                    const int wb0 = ee[0].y, wb1 = ee[1].y;
                    const int wb2 = ee[2].y, wb3 = ee[3].y;
                    if (b + 1 < nfull) {
                        const int pn = p + 4 * (b + 1);
#pragma unroll
                        for (int j = 0; j < 4; ++j) ee[j] = __ldg(&g_epack[pn + j]);
                    }
                    __half2 a01, a23, b01, b23, c01, c23, d01, d23;
                    EDGE_CORE(rv[0], hh[0], wb0, a01, a23);
                    EDGE_CORE(rv[1], hh[1], wb1, b01, b23);
                    EDGE_CORE(rv[2], hh[2], wb2, c01, c23);
                    EDGE_CORE(rv[3], hh[3], wb3, d01, d23);
                    const __half2 t01 = __hadd2(__hadd2(a01, b01), __hadd2(c01, d01));
                    const __half2 t23 = __hadd2(__hadd2(a23, b23), __hadd2(c23, d23));
                    sum01 = add2(sum01, h2f2(t01));
                    sum23 = add2(sum23, h2f2(t23));
                }
                p += nfull * 4;
            }
            for (; p < e_; ++p) {
                const int2 e0 = __ldg(&g_epack[p]);
                const uint2 rv0 = __ldg(&relin[(e0.x >> 16) * DD]);
                const uint2 hh0 = ldcg2u(&h16_in[(e0.x & 0xFFFF) * DD + d]);
                __half2 a01, a23;
                EDGE_CORE(rv0, hh0, e0.y, a01, a23);
                sum01 = add2(sum01, h2f2(a01));
                sum23 = add2(sum23, h2f2(a23));
            }

            if (half) {
                mgS[s][lane][0] = sum01;
                mgS[s][lane][1] = sum23;
                sqS[s][lane] = make_uint2(h2u(sqh01), h2u(sqh23));
                mxS[s][lane] = make_uint2(h2u(mxh01), h2u(mxh23));
                mnS[s][lane] = make_uint2(h2u(mnh01), h2u(mnh23));
            }
            __syncthreads();
            if (half == 0) {
                sum01 = add2(sum01, mgS[s][lane][0]);
                sum23 = add2(sum23, mgS[s][lane][1]);
                const uint2 qq = sqS[s][lane];
                sqh01 = __hadd2(sqh01, u2h(qq.x));
                sqh23 = __hadd2(sqh23, u2h(qq.y));
                const uint2 xx = mxS[s][lane];
                mxh01 = __hmax2(mxh01, u2h(xx.x));
                mxh23 = __hmax2(mxh23, u2h(xx.y));
                const uint2 nn = mnS[s][lane];
                mnh01 = __hmin2(mnh01, u2h(nn.x));
                mnh23 = __hmin2(mnh23, u2h(nn.y));

                const float2 s01 = unpk(sum01), s23 = unpk(sum23);
                const float2 q01 = __half22float2(sqh01), q23 = __half22float2(sqh23);
                const float2 x01 = __half22float2(mxh01), x23 = __half22float2(mxh23);
                const float2 n01 = __half22float2(mnh01), n23 = __half22float2(mnh23);
                sumF = make_float4(s01.x, s01.y, s23.x, s23.y);
                sqF  = make_float4(q01.x, q01.y, q23.x, q23.y);
                mxF  = make_float4(x01.x, x01.y, x23.x, x23.y);
                mnF  = make_float4(n01.x, n01.y, n23.x, n23.y);
                have_stats = true;
            }
        }

        if (layer == 0) __syncthreads();   // match the layer>0 merge sync

        if (half == 0 && lane == 0) { s_act[s] = act; s_scl[s] = g_sc[v]; }

        if (have_stats) {
            const float inv = 1.0f / (float)(degv + 1);
            float4 mean, var, sd2;
            mean.x = sumF.x * inv; mean.y = sumF.y * inv; mean.z = sumF.z * inv; mean.w = sumF.w * inv;
            var.x = sqF.x * inv - mean.x * mean.x; var.y = sqF.y * inv - mean.y * mean.y;
            var.z = sqF.z * inv - mean.z * mean.z; var.w = sqF.w * inv - mean.w * mean.w;
            sd2.x = sqrtf(fmaxf(var.x, EPSF)); sd2.y = sqrtf(fmaxf(var.y, EPSF));
            sd2.z = sqrtf(fmaxf(var.z, EPSF)); sd2.w = sqrtf(fmaxf(var.w, EPSF));
            const float2 sc = g_sc[v];
            const int r0 = s * 4;

            float4 hv1;
            hv1.x = __shfl_down_sync(0xffffffffu, hv.x, 1);
            hv1.y = __shfl_down_sync(0xffffffffu, hv.y, 1);
            hv1.z = __shfl_down_sync(0xffffffffu, hv.z, 1);
            hv1.w = __shfl_down_sync(0xffffffffu, hv.w, 1);
            if ((d & 1) == 0) WRITE_PAIR(d >> 1, hv, hv1);

            float4 f[12];
            const float4 st4[4] = {mean, mxF, mnF, sd2};
#pragma unroll
            for (int si = 0; si < 4; ++si) {
                const float4 fv = st4[si];
                f[si * 3 + 0] = fv;
                f[si * 3 + 1] = make_float4(fv.x * sc.x, fv.y * sc.x, fv.z * sc.x, fv.w * sc.x);
                f[si * 3 + 2] = make_float4(fv.x * sc.y, fv.y * sc.y, fv.z * sc.y, fv.w * sc.y);
            }
            const int pb = 16 + 6 * d;
#pragma unroll
            for (int pi = 0; pi < 6; ++pi)
                WRITE_PAIR(pb + pi, f[2 * pi], f[2 * pi + 1]);
        }
    }
    __syncthreads();

    const int anyact = s_act[0] | s_act[1] | s_act[2] | s_act[3];

    // ---- GEMM via mma.sync bf16 3-split (even warps, gw = w>>1) ----
    float d0 = 0.f, d1 = 0.f, d2 = 0.f, d3 = 0.f;
    const int c = lane & 3, g = lane >> 2;
    const int gw = w >> 1;
    if (anyact && half == 0) {
        const uint4* Wp = g_Wmma + (size_t)layer * NSTEP * 128 + (gw * 32 + lane);
#pragma unroll
        for (int st = 0; st < NSTEP; ++st) {
            const uint4 wv = __ldg(&Wp[(size_t)st * 128]);
            const int pA = st * 8 + c, pB = st * 8 + 4 + c;
            const uint32_t ah0 = catH[pA][g], ah1 = catH[pA][g + 8];
            const uint32_t ah2 = catH[pB][g], ah3 = catH[pB][g + 8];
            const uint32_t al0 = catL[pA][g], al1 = catL[pA][g + 8];
            const uint32_t al2 = catL[pB][g], al3 = catL[pB][g + 8];
            mma16816(d0, d1, d2, d3, ah0, ah1, ah2, ah3, wv.x, wv.y);
            mma16816(d0, d1, d2, d3, ah0, ah1, ah2, ah3, wv.z, wv.w);
            mma16816(d0, d1, d2, d3, al0, al1, al2, al3, wv.x, wv.y);
        }
    }
    __syncthreads();    // all done reading catL before sD overwrites it
    if (anyact && half == 0) {
        const int j0 = 8 * gw + 2 * c;
        sD[g * 33 + j0] = d0;       sD[g * 33 + j0 + 1] = d1;
        sD[(g + 8) * 33 + j0] = d2; sD[(g + 8) * 33 + j0 + 1] = d3;
    }
    __syncthreads();

    // ---- epilogue (even warps; warp gw writes node slot gw) ----
    if (half == 0) {
        const float bias = lin_b[layer * DD + lane];
        float4 o;
        if (s_act[gw]) {
            o = make_float4(fmaxf(sD[(gw * 4 + 0) * 33 + lane] + bias, 0.0f),
                            fmaxf(sD[(gw * 4 + 1) * 33 + lane] + bias, 0.0f),
                            fmaxf(sD[(gw * 4 + 2) * 33 + lane] + bias, 0.0f),
                            fmaxf(sD[(gw * 4 + 3) * 33 + lane] + bias, 0.0f));
        } else {
            const float sd = sqrtf(EPSF);
            const float2 sc = s_scl[gw];
            const float c2 = g_csum[lane] + sc.x * g_csum[DD + lane] + sc.y * g_csum[2 * DD + lane];
            const float val = fmaxf(bias + sd * c2, 0.0f);
            o = make_float4(val, val, val, val);
        }
        const __half2 o01 = __floats2half2_rn(o.x, o.y);
        const __half2 o23 = __floats2half2_rn(o.z, o.w);
        uint2 ho;
        ho.x = h2u(o01);
        ho.y = h2u(o23);
        h16_out[(blockIdx.x * 4 + gw) * DD + lane] = ho;
    }
}

// ---------------- final MLP scoring (reads fp16 hidden) ----------------
__global__ void __launch_bounds__(256) mlp_kernel(
    const uint2* __restrict__ hid16,
    const float* __restrict__ W1, const float* __restrict__ b1,
    const float* __restrict__ W2, const float* __restrict__ b2,
    float* __restrict__ out)
{
    __shared__ float  W1s[64 * 64];
    __shared__ float  W2s[64];
    __shared__ float  b1s[64];
    __shared__ float4 f2[NPB * 64];

    const int t = threadIdx.x;
    for (int i = t; i < 64 * 64; i += 256) W1s[i] = W1[i];
    if (t < 64) { W2s[t] = W2[t]; b1s[t] = b1[t]; }

    const int s = t >> 5, lane = t & 31;

    for (int it = 0; it < MLP_IT; ++it) {
        const int vbase = (blockIdx.x * MLP_IT + it) * NPB;
        if (vbase >= NN) break;
        __syncthreads();
        for (int i = t; i < NPB * 64; i += 256) {
            const int k = i & 63;
            const int sl = i >> 6;
            const int v = vbase + sl;
            float4 val = make_float4(0.f, 0.f, 0.f, 0.f);
            if (v < NN) val = (k < DD) ? cvt_rv(__ldg(&hid16[v * DD + k])) : g_qT[k - DD];
            f2[i] = val;
        }
        __syncthreads();

        const int v = vbase + s;
        if (v < NN) {
            ull a01 = dup2(b1s[lane]),      a23 = a01;
            ull b01 = dup2(b1s[lane + 32]), b23 = b01;
            const ulonglong2* up = (const ulonglong2*)&f2[s * 64];
#pragma unroll 8
            for (int k = 0; k < 64; ++k) {
                const ulonglong2 u = up[k];
                const ull wa = dup2(W1s[k * 64 + lane]);
                const ull wb = dup2(W1s[k * 64 + lane + 32]);
                a01 = fma2(u.x, wa, a01); a23 = fma2(u.y, wa, a23);
                b01 = fma2(u.x, wb, b01); b23 = fma2(u.y, wb, b23);
            }
            const float2 fa01 = unpk(a01), fa23 = unpk(a23);
            const float2 fb01 = unpk(b01), fb23 = unpk(b23);
            const float accA[4] = {fa01.x, fa01.y, fa23.x, fa23.y};
            const float accB[4] = {fb01.x, fb01.y, fb23.x, fb23.y};
            const float w2a = W2s[lane], w2b = W2s[lane + 32];
            const float bias2 = b2[0];
#pragma unroll
            for (int bb = 0; bb < 4; ++bb) {
                float p = fmaxf(accA[bb], 0.0f) * w2a + fmaxf(accB[bb], 0.0f) * w2b;
#pragma unroll
                for (int off = 16; off > 0; off >>= 1)
                    p += __shfl_down_sync(0xffffffffu, p, off);
                if (lane == 0) out[bb * NN + v] = p + bias2;
            }
        }
    }
}

// ---------------- launch ----------------
extern "C" void kernel_launch(void* const* d_in, const int* in_sizes, int n_in,
                              void* d_out, int out_size) {
    const int*   node_in     = (const int*)  d_in[0];
    const int*   node_out    = (const int*)  d_in[1];
    const int*   relation    = (const int*)  d_in[2];
    const float* edge_weight = (const float*)d_in[3];
    const int*   h_index     = (const int*)  d_in[4];
    const int*   r_index     = (const int*)  d_in[5];
    const float* query_embed = (const float*)d_in[6];
    const float* rel_W  = (const float*)d_in[7];
    const float* rel_b  = (const float*)d_in[8];
    const float* lin_W  = (const float*)d_in[9];
    const float* lin_b  = (const float*)d_in[10];
    const float* mlp_W1 = (const float*)d_in[11];
    const float* mlp_b1 = (const float*)d_in[12];
    const float* mlp_W2 = (const float*)d_in[13];
    const float* mlp_b2 = (const float*)d_in[14];
    float* out = (float*)d_out;

    uint2 *h16A, *h16B;
    cudaGetSymbolAddress((void**)&h16A, g_h16A);
    cudaGetSymbolAddress((void**)&h16B, g_h16B);

    setup_kernel<<<SB_TOTAL, 128>>>(h_index, r_index, query_embed,
                                    lin_W, rel_W, rel_b);       // 0
    hist_kernel<<<(NE + 255) / 256, 256>>>(node_out, edge_weight); // 1
    scan_kernel<<<SCAN_B, 1024>>>();                            // 2
    scatter_kernel<<<(NE + 255) / 256, 256>>>(node_in, node_out, relation, edge_weight); // 3

    const uint2* h16in = h16A;       // unused at layer 0
    uint2* h16outs[4] = {h16A, h16B, h16A, h16B};
    for (int l = 0; l < NL; ++l) {
        conv_kernel<<<NN / 4, 256>>>(lin_b, h16in, h16outs[l], h_index, l); // 4..7
        h16in = h16outs[l];
    }
    mlp_kernel<<<(NN + NPB * MLP_IT - 1) / (NPB * MLP_IT), 256>>>(
        h16in, mlp_W1, mlp_b1, mlp_W2, mlp_b2, out);            // 8
}

// round 14
// speedup vs baseline: 1.1217x; 1.1217x over previous
#include <cuda_runtime.h>
#include <cuda_fp16.h>
#include <math.h>
#include <stdint.h>

#define NN 25000
#define NE 500000
#define BQ 4
#define DD 32
#define RR 474
#define NL 4
#define KD 416          // 13*D
#define NSTEP 26        // KD/16 k-steps
#define EPSF 1e-6f
#define NPB 8           // nodes per mlp inner batch
#define MLP_IT 8        // batches per mlp block
#define SCAN_B 25       // ceil(25000/1024)

// setup_kernel block partition
#define SB_RELIN (NL * RR)                 // 1896
#define SB_WSPLIT (SB_RELIN + NL * NSTEP)  // +104
#define SB_ZERO (SB_WSPLIT + 25)           // +25 (zero cnt/deg/flags)
#define SB_TOTAL (SB_ZERO + 1)             // +1 (init)

typedef unsigned long long ull;

// ---- packed fp32x2 helpers ----
__device__ __forceinline__ ull fma2(ull a, ull b, ull c) {
    ull d; asm("fma.rn.f32x2 %0,%1,%2,%3;" : "=l"(d) : "l"(a), "l"(b), "l"(c)); return d;
}
__device__ __forceinline__ ull add2(ull a, ull b) {
    ull d; asm("add.rn.f32x2 %0,%1,%2;" : "=l"(d) : "l"(a), "l"(b)); return d;
}
__device__ __forceinline__ ull pk2(float x, float y) {
    ull r; asm("mov.b64 %0,{%1,%2};" : "=l"(r) : "f"(x), "f"(y)); return r;
}
__device__ __forceinline__ ull dup2(float x) {
    ull r; asm("mov.b64 %0,{%1,%1};" : "=l"(r) : "f"(x)); return r;
}
__device__ __forceinline__ float2 unpk(ull a) {
    float2 f; asm("mov.b64 {%0,%1},%2;" : "=f"(f.x), "=f"(f.y) : "l"(a)); return f;
}
__device__ __forceinline__ ull h2f2(__half2 h) {
    const float2 f = __half22float2(h);
    return pk2(f.x, f.y);
}
__device__ __forceinline__ __half2 u2h(uint32_t u) { return *(const __half2*)&u; }
__device__ __forceinline__ uint32_t h2u(__half2 h) { return *(const uint32_t*)&h; }
__device__ __forceinline__ float4 cvt_rv(const uint2 rh) {
    const float2 f01 = __half22float2(u2h(rh.x));
    const float2 f23 = __half22float2(u2h(rh.y));
    return make_float4(f01.x, f01.y, f23.x, f23.y);
}

// split (x0,x1) into bf16 hi pair + bf16 lo pair (lo = x - float(hi))
__device__ __forceinline__ void split2(float x0, float x1, uint32_t& h, uint32_t& l) {
    uint32_t hp; asm("cvt.rn.bf16x2.f32 %0,%1,%2;" : "=r"(hp) : "f"(x1), "f"(x0));
    const float l0 = x0 - __int_as_float(hp << 16);
    const float l1 = x1 - __int_as_float(hp & 0xFFFF0000u);
    uint32_t lp; asm("cvt.rn.bf16x2.f32 %0,%1,%2;" : "=r"(lp) : "f"(l1), "f"(l0));
    h = hp; l = lp;
}

__device__ __forceinline__ void mma16816(float& d0, float& d1, float& d2, float& d3,
                                         uint32_t a0, uint32_t a1, uint32_t a2, uint32_t a3,
                                         uint32_t b0, uint32_t b1) {
    asm volatile("mma.sync.aligned.m16n8k16.row.col.f32.bf16.bf16.f32 "
                 "{%0,%1,%2,%3},{%4,%5,%6,%7},{%8,%9},{%0,%1,%2,%3};"
                 : "+f"(d0), "+f"(d1), "+f"(d2), "+f"(d3)
                 : "r"(a0), "r"(a1), "r"(a2), "r"(a3), "r"(b0), "r"(b1));
}

// ---------------- scratch ----------------
__device__ int    g_cnt[NN];
__device__ float  g_deg[NN];
__device__ int    g_rowptr[NN + 1];
__device__ int    g_pos[NN];
__device__ int2   g_epack[NE];          // CSR-ordered (nin | rel<<16, w_bits)
__device__ float2 g_sc[NN];             // (s1, s2)
__device__ int    g_flag[SCAN_B];
__device__ int    g_partI[SCAN_B];
__device__ float  g_partF[SCAN_B];
__device__ uint2  g_h16A[NN * DD];      // fp16x2 hidden state
__device__ uint2  g_h16B[NN * DD];
__device__ uint2  g_relinH[NL * RR * DD]; // fp16x2 pairs: (b0,b1),(b2,b3)
__device__ float4 g_qT[DD];             // [d] -> b-vector
__device__ float  g_csum[3 * DD];       // layer-0 std-column sums per scale
__device__ uint4  g_Wmma[NL * NSTEP * 128]; // fragment-ordered split weights

// ---------------- fused setup (input-only work, launch #0) ----------------
__global__ void __launch_bounds__(128) setup_kernel(
    const int* __restrict__ h_index,
    const int* __restrict__ r_index,
    const float* __restrict__ query_embed,
    const float* __restrict__ lin_W,
    const float* __restrict__ rel_W,
    const float* __restrict__ rel_b)
{
    const int bx = blockIdx.x;
    const int t = threadIdx.x;

    if (bx < SB_RELIN) {
        __shared__ float acc_s[BQ][DD];
        const int l = bx / RR, r = bx - l * RR;
        const int d = t & 31, b = t >> 5;
        const int ri = __ldg(&r_index[b]);
        const float* W = rel_W + (size_t)l * DD * RR * DD + (size_t)r * DD + d;
        float acc = rel_b[(size_t)l * RR * DD + r * DD + d];
#pragma unroll
        for (int k = 0; k < DD; ++k)
            acc += __ldg(&query_embed[ri * DD + k]) * W[(size_t)k * RR * DD];
        acc_s[b][d] = acc;
        __syncthreads();
        if (t < DD) {
            const __half2 p01 = __floats2half2_rn(acc_s[0][t], acc_s[1][t]);
            const __half2 p23 = __floats2half2_rn(acc_s[2][t], acc_s[3][t]);
            uint2 o;
            o.x = h2u(p01);
            o.y = h2u(p23);
            g_relinH[(size_t)(l * RR + r) * DD + t] = o;
        }
    } else if (bx < SB_WSPLIT) {
        const int i = bx - SB_RELIN;
        const int l = i / NSTEP, s = i % NSTEP;
        const int w = t >> 5, lane = t & 31;
        const int c = lane & 3, n = 8 * w + (lane >> 2);
        const int k0 = 16 * s;
        const float* W = lin_W + (size_t)l * KD * DD;
        const float w00 = W[(k0 + 2 * c) * DD + n];
        const float w01 = W[(k0 + 2 * c + 1) * DD + n];
        const float w10 = W[(k0 + 8 + 2 * c) * DD + n];
        const float w11 = W[(k0 + 9 + 2 * c) * DD + n];
        uint32_t h0, l0, h1, l1;
        split2(w00, w01, h0, l0);
        split2(w10, w11, h1, l1);
        g_Wmma[(size_t)(l * NSTEP + s) * 128 + t] = make_uint4(h0, h1, l0, l1);
    } else if (bx < SB_ZERO) {
        const int bi = bx - SB_WSPLIT;
        const int base = bi * 1000;
        for (int i = base + t; i < base + 1000 && i < NN; i += 128) {
            g_cnt[i] = 0;
            g_deg[i] = 0.0f;
        }
        if (bi == 0 && t < SCAN_B) g_flag[t] = 0;
    } else {
        if (t < 128) {
            const int b = t >> 5, d = t & 31;
            ((float*)g_qT)[d * 4 + b] = __ldg(&query_embed[__ldg(&r_index[b]) * DD + d]);
        }
        __syncthreads();
        if (t < DD) {
            const int j = t;
#pragma unroll
            for (int s = 0; s < 3; ++s) {
                float c = 0.0f;
#pragma unroll
                for (int dd = 0; dd < DD; ++dd)
                    c += lin_W[(DD + (4 * dd + 3) * 3 + s) * DD + j];
                g_csum[s * DD + j] = c;
            }
        }
    }
}

// ---------------- graph-build kernels ----------------
__global__ void hist_kernel(const int* __restrict__ node_out,
                            const float* __restrict__ ew) {
    const int e = blockIdx.x * 256 + threadIdx.x;
    if (e < NE) {
        const int v = node_out[e];
        atomicAdd(&g_cnt[v], 1);
        atomicAdd(&g_deg[v], ew[e]);
    }
}

// single-kernel decoupled scan: local scan + publish partial + poll all flags
__global__ void __launch_bounds__(1024) scan_kernel() {
    __shared__ int wsum[32];
    __shared__ int woff[32];
    __shared__ float lsum[32];
    __shared__ int sI[SCAN_B];
    __shared__ float sF[SCAN_B];
    const int t = threadIdx.x, wid = t >> 5, lane = t & 31;
    const int b = blockIdx.x;
    const int i = b * 1024 + t;
    const int x = (i < NN) ? g_cnt[i] : 0;
    float y = (i < NN) ? logf(g_deg[i] + 1.0f) : 0.0f;

    int incl = x;
#pragma unroll
    for (int off = 1; off < 32; off <<= 1) {
        int n = __shfl_up_sync(0xffffffffu, incl, off);
        if (lane >= off) incl += n;
    }
#pragma unroll
    for (int off = 16; off > 0; off >>= 1)
        y += __shfl_down_sync(0xffffffffu, y, off);
    if (lane == 31) wsum[wid] = incl;
    if (lane == 0)  lsum[wid] = y;
    __syncthreads();
    if (wid == 0) {
        int s = wsum[lane];
        int si = s;
#pragma unroll
        for (int off = 1; off < 32; off <<= 1) {
            int n = __shfl_up_sync(0xffffffffu, si, off);
            if (lane >= off) si += n;
        }
        woff[lane] = si - s;
        if (lane == 31) g_partI[b] = si;   // block int total
    }
    __syncthreads();
    if (t == 0) {
        float ftot = 0.0f;
#pragma unroll
        for (int ww = 0; ww < 32; ++ww) ftot += lsum[ww];
        g_partF[b] = ftot;
        __threadfence();
        atomicExch(&g_flag[b], 1);
    }
    // poll all partials (25 blocks always co-resident on 148 SMs)
    if (t < SCAN_B) {
        while (atomicAdd(&g_flag[t], 0) == 0) {}
        sI[t] = g_partI[t];
        sF[t] = g_partF[t];
    }
    __syncthreads();
    int off = 0;
    float gl = 0.0f;
#pragma unroll
    for (int j = 0; j < SCAN_B; ++j) {
        if (j < b) off += sI[j];
        gl += sF[j];
    }
    if (i < NN) {
        const int rp = incl - x + woff[wid] + off;
        g_rowptr[i] = rp;
        g_pos[i] = rp;
        const float mean = gl / (float)NN;
        const float s = logf(g_deg[i] + 1.0f) / mean;
        g_sc[i] = make_float2(s, 1.0f / fmaxf(s, 0.01f));
    }
    if (i == 0) g_rowptr[NN] = NE;
}

__global__ void scatter_kernel(const int* __restrict__ node_in,
                               const int* __restrict__ node_out,
                               const int* __restrict__ relation,
                               const float* __restrict__ ew) {
    const int e = blockIdx.x * 256 + threadIdx.x;
    if (e < NE) {
        const int p = atomicAdd(&g_pos[node_out[e]], 1);
        g_epack[p] = make_int2(node_in[e] | (relation[e] << 16),
                               __float_as_int(ew[e]));
    }
}

// ---------------- fused conv layer (R12-proven structure) ----------------
__device__ __forceinline__ uint2 ldcg2u(const uint2* p) {
    uint2 v;
    asm volatile("ld.global.cg.v2.u32 {%0,%1},[%2];"
                 : "=r"(v.x), "=r"(v.y) : "l"(p));
    return v;
}

#define WRITE_PAIR(p, x0, x1)                                              \
    do {                                                                   \
        uint32_t hh_, ll_;                                                 \
        split2((x0).x, (x1).x, hh_, ll_);                                  \
        catH[p][r0] = hh_; catL[p][r0] = ll_;                              \
        split2((x0).y, (x1).y, hh_, ll_);                                  \
        catH[p][r0 + 1] = hh_; catL[p][r0 + 1] = ll_;                      \
        split2((x0).z, (x1).z, hh_, ll_);                                  \
        catH[p][r0 + 2] = hh_; catL[p][r0 + 2] = ll_;                      \
        split2((x0).w, (x1).w, hh_, ll_);                                  \
        catH[p][r0 + 3] = hh_; catL[p][r0 + 3] = ll_;                      \
    } while (0)

// core edge update: sq/max/min accumulate in half2; weighted message returned
#define EDGE_CORE(rv_, hh_, wbits_, mw01o, mw23o)                          \
    do {                                                                   \
        const __half2 wh_ = __float2half2_rn(__int_as_float(wbits_));      \
        const __half2 m01_ = __hmul2(u2h((rv_).x), u2h((hh_).x));          \
        const __half2 m23_ = __hmul2(u2h((rv_).y), u2h((hh_).y));          \
        mw01o = __hmul2(m01_, wh_);                                        \
        mw23o = __hmul2(m23_, wh_);                                        \
        mxh01 = __hmax2(mxh01, mw01o); mxh23 = __hmax2(mxh23, mw23o);      \
        mnh01 = __hmin2(mnh01, mw01o); mnh23 = __hmin2(mnh23, mw23o);      \
        sqh01 = __hfma2(m01_, mw01o, sqh01);                               \
        sqh23 = __hfma2(m23_, mw23o, sqh23);                               \
    } while (0)

__global__ void __launch_bounds__(128) conv_kernel(
    const float* __restrict__ lin_b,
    const uint2* __restrict__ h16_in, uint2* __restrict__ h16_out,
    const int* __restrict__ h_index, int layer)
{
    __shared__ uint32_t catH[KD / 2][17];   // 14.1KB
    __shared__ uint32_t catL[KD / 2][17];   // 14.1KB (sD aliases post-GEMM)
    __shared__ int s_act[4];
    __shared__ float2 s_scl[4];
    float* sD = (float*)catL;

    const int t = threadIdx.x, w = t >> 5, lane = t & 31;
    const int v = blockIdx.x * 4 + w;
    const int d = lane;
    const uint2* relin = g_relinH + (size_t)layer * RR * DD + d;

    // ---- message phase (warp per node) ----
    {
        const int4 h = *(const int4*)h_index;
        const float4 q = g_qT[d];
        const float4 m0 = make_float4(v == h.x ? q.x : 0.f,
                                      v == h.y ? q.y : 0.f,
                                      v == h.z ? q.z : 0.f,
                                      v == h.w ? q.w : 0.f);
        int p = g_rowptr[v];
        const int e_ = g_rowptr[v + 1];
        const int degv = e_ - p;
        int act;
        float4 hv;
        float4 sumF, sqF, mxF, mnF;

        if (layer == 0) {
            hv = m0;   // layer-0 hidden IS the boundary
            float4 sum = m0, mx = m0, mn = m0;
            float4 sq = make_float4(m0.x * m0.x, m0.y * m0.y, m0.z * m0.z, m0.w * m0.w);
            act = (v == h.x) | (v == h.y) | (v == h.z) | (v == h.w);
            int nacc = 0;
            for (; p < e_; ++p) {
                const int2 ep = __ldg(&g_epack[p]);
                const int nin = ep.x & 0xFFFF;
                if (nin == h.x || nin == h.y || nin == h.z || nin == h.w) {
                    act = 1; ++nacc;
                    const uint2 rvh = __ldg(&relin[(ep.x >> 16) * DD]);
                    const float2 r01 = __half22float2(u2h(rvh.x));
                    const float2 r23 = __half22float2(u2h(rvh.y));
                    const float4 hh = make_float4(nin == h.x ? q.x : 0.f,
                                                  nin == h.y ? q.y : 0.f,
                                                  nin == h.z ? q.z : 0.f,
                                                  nin == h.w ? q.w : 0.f);
                    const float wgt = __int_as_float(ep.y);
                    float m, mw;
                    m = r01.x * hh.x; mw = m * wgt; sum.x += mw; sq.x = fmaf(m, mw, sq.x); mx.x = fmaxf(mx.x, mw); mn.x = fminf(mn.x, mw);
                    m = r01.y * hh.y; mw = m * wgt; sum.y += mw; sq.y = fmaf(m, mw, sq.y); mx.y = fmaxf(mx.y, mw); mn.y = fminf(mn.y, mw);
                    m = r23.x * hh.z; mw = m * wgt; sum.z += mw; sq.z = fmaf(m, mw, sq.z); mx.z = fmaxf(mx.z, mw); mn.z = fminf(mn.z, mw);
                    m = r23.y * hh.w; mw = m * wgt; sum.w += mw; sq.w = fmaf(m, mw, sq.w); mx.w = fmaxf(mx.w, mw); mn.w = fminf(mn.w, mw);
                }
            }
            if (nacc < degv) {
                mx.x = fmaxf(mx.x, 0.f); mx.y = fmaxf(mx.y, 0.f); mx.z = fmaxf(mx.z, 0.f); mx.w = fmaxf(mx.w, 0.f);
                mn.x = fminf(mn.x, 0.f); mn.y = fminf(mn.y, 0.f); mn.z = fminf(mn.z, 0.f); mn.w = fminf(mn.w, 0.f);
            }
            sumF = sum; sqF = sq; mxF = mx; mnF = mn;
        } else {
            act = 1;
            hv = cvt_rv(__ldg(&h16_in[v * DD + d]));
            ull sum01 = pk2(m0.x, m0.y), sum23 = pk2(m0.z, m0.w);
            __half2 sqh01 = __floats2half2_rn(m0.x * m0.x, m0.y * m0.y);
            __half2 sqh23 = __floats2half2_rn(m0.z * m0.z, m0.w * m0.w);
            __half2 mxh01 = __floats2half2_rn(m0.x, m0.y);
            __half2 mxh23 = __floats2half2_rn(m0.z, m0.w);
            __half2 mnh01 = mxh01, mnh23 = mxh23;

            const int nfull = (e_ - p) >> 2;
            if (nfull > 0) {
                int2 ee[4];
#pragma unroll
                for (int j = 0; j < 4; ++j) ee[j] = __ldg(&g_epack[p + j]);
                for (int b = 0; b < nfull; ++b) {
                    uint2 rv[4], hh[4];
#pragma unroll
                    for (int j = 0; j < 4; ++j) {
                        rv[j] = __ldg(&relin[(ee[j].x >> 16) * DD]);
                        hh[j] = ldcg2u(&h16_in[(ee[j].x & 0xFFFF) * DD + d]);
                    }
                    const int wb0 = ee[0].y, wb1 = ee[1].y;
                    const int wb2 = ee[2].y, wb3 = ee[3].y;
                    if (b + 1 < nfull) {
                        const int pn = p + 4 * (b + 1);
#pragma unroll
                        for (int j = 0; j < 4; ++j) ee[j] = __ldg(&g_epack[pn + j]);
                    }
                    __half2 a01, a23, b01, b23, c01, c23, d01, d23;
                    EDGE_CORE(rv[0], hh[0], wb0, a01, a23);
                    EDGE_CORE(rv[1], hh[1], wb1, b01, b23);
                    EDGE_CORE(rv[2], hh[2], wb2, c01, c23);
                    EDGE_CORE(rv[3], hh[3], wb3, d01, d23);
                    const __half2 t01 = __hadd2(__hadd2(a01, b01), __hadd2(c01, d01));
                    const __half2 t23 = __hadd2(__hadd2(a23, b23), __hadd2(c23, d23));
                    sum01 = add2(sum01, h2f2(t01));
                    sum23 = add2(sum23, h2f2(t23));
                }
                p += nfull * 4;
            }
            for (; p < e_; ++p) {
                const int2 e0 = __ldg(&g_epack[p]);
                const uint2 rv0 = __ldg(&relin[(e0.x >> 16) * DD]);
                const uint2 hh0 = ldcg2u(&h16_in[(e0.x & 0xFFFF) * DD + d]);
                __half2 a01, a23;
                EDGE_CORE(rv0, hh0, e0.y, a01, a23);
                sum01 = add2(sum01, h2f2(a01));
                sum23 = add2(sum23, h2f2(a23));
            }
            const float2 s01 = unpk(sum01), s23 = unpk(sum23);
            const float2 q01 = __half22float2(sqh01), q23 = __half22float2(sqh23);
            const float2 x01 = __half22float2(mxh01), x23 = __half22float2(mxh23);
            const float2 n01 = __half22float2(mnh01), n23 = __half22float2(mnh23);
            sumF = make_float4(s01.x, s01.y, s23.x, s23.y);
            sqF  = make_float4(q01.x, q01.y, q23.x, q23.y);
            mxF  = make_float4(x01.x, x01.y, x23.x, x23.y);
            mnF  = make_float4(n01.x, n01.y, n23.x, n23.y);
        }

        if (lane == 0) { s_act[w] = act; s_scl[w] = g_sc[v]; }

        if (act) {
            const float inv = 1.0f / (float)(degv + 1);
            float4 mean, var, sd2;
            mean.x = sumF.x * inv; mean.y = sumF.y * inv; mean.z = sumF.z * inv; mean.w = sumF.w * inv;
            var.x = sqF.x * inv - mean.x * mean.x; var.y = sqF.y * inv - mean.y * mean.y;
            var.z = sqF.z * inv - mean.z * mean.z; var.w = sqF.w * inv - mean.w * mean.w;
            sd2.x = sqrtf(fmaxf(var.x, EPSF)); sd2.y = sqrtf(fmaxf(var.y, EPSF));
            sd2.z = sqrtf(fmaxf(var.z, EPSF)); sd2.w = sqrtf(fmaxf(var.w, EPSF));
            const float2 sc = g_sc[v];
            const int r0 = w * 4;

            float4 hv1;
            hv1.x = __shfl_down_sync(0xffffffffu, hv.x, 1);
            hv1.y = __shfl_down_sync(0xffffffffu, hv.y, 1);
            hv1.z = __shfl_down_sync(0xffffffffu, hv.z, 1);
            hv1.w = __shfl_down_sync(0xffffffffu, hv.w, 1);
            if ((d & 1) == 0) WRITE_PAIR(d >> 1, hv, hv1);

            float4 f[12];
            const float4 st4[4] = {mean, mxF, mnF, sd2};
#pragma unroll
            for (int si = 0; si < 4; ++si) {
                const float4 fv = st4[si];
                f[si * 3 + 0] = fv;
                f[si * 3 + 1] = make_float4(fv.x * sc.x, fv.y * sc.x, fv.z * sc.x, fv.w * sc.x);
                f[si * 3 + 2] = make_float4(fv.x * sc.y, fv.y * sc.y, fv.z * sc.y, fv.w * sc.y);
            }
            const int pb = 16 + 6 * d;
#pragma unroll
            for (int pi = 0; pi < 6; ++pi)
                WRITE_PAIR(pb + pi, f[2 * pi], f[2 * pi + 1]);
        }
    }
    __syncthreads();

    const int anyact = s_act[0] | s_act[1] | s_act[2] | s_act[3];

    // ---- GEMM via mma.sync bf16 3-split (accumulate in regs) ----
    float d0 = 0.f, d1 = 0.f, d2 = 0.f, d3 = 0.f;
    const int c = lane & 3, g = lane >> 2;
    if (anyact) {
        const uint4* Wp = g_Wmma + (size_t)layer * NSTEP * 128 + (w * 32 + lane);
#pragma unroll
        for (int s = 0; s < NSTEP; ++s) {
            const uint4 wv = __ldg(&Wp[(size_t)s * 128]);
            const int pA = s * 8 + c, pB = s * 8 + 4 + c;
            const uint32_t ah0 = catH[pA][g], ah1 = catH[pA][g + 8];
            const uint32_t ah2 = catH[pB][g], ah3 = catH[pB][g + 8];
            const uint32_t al0 = catL[pA][g], al1 = catL[pA][g + 8];
            const uint32_t al2 = catL[pB][g], al3 = catL[pB][g + 8];
            mma16816(d0, d1, d2, d3, ah0, ah1, ah2, ah3, wv.x, wv.y);
            mma16816(d0, d1, d2, d3, ah0, ah1, ah2, ah3, wv.z, wv.w);
            mma16816(d0, d1, d2, d3, al0, al1, al2, al3, wv.x, wv.y);
        }
    }
    __syncthreads();    // all warps done READING catL before sD overwrites it
    if (anyact) {
        const int j0 = 8 * w + 2 * c;
        sD[g * 33 + j0] = d0;       sD[g * 33 + j0 + 1] = d1;
        sD[(g + 8) * 33 + j0] = d2; sD[(g + 8) * 33 + j0 + 1] = d3;
    }
    __syncthreads();

    // ---- epilogue: fp16 hidden only ----
    {
        const float bias = lin_b[layer * DD + lane];
        float4 o;
        if (s_act[w]) {
            o = make_float4(fmaxf(sD[(w * 4 + 0) * 33 + lane] + bias, 0.0f),
                            fmaxf(sD[(w * 4 + 1) * 33 + lane] + bias, 0.0f),
                            fmaxf(sD[(w * 4 + 2) * 33 + lane] + bias, 0.0f),
                            fmaxf(sD[(w * 4 + 3) * 33 + lane] + bias, 0.0f));
        } else {
            const float sd = sqrtf(EPSF);
            const float2 sc = s_scl[w];
            const float c2 = g_csum[lane] + sc.x * g_csum[DD + lane] + sc.y * g_csum[2 * DD + lane];
            const float val = fmaxf(bias + sd * c2, 0.0f);
            o = make_float4(val, val, val, val);
        }
        const __half2 o01 = __floats2half2_rn(o.x, o.y);
        const __half2 o23 = __floats2half2_rn(o.z, o.w);
        uint2 ho;
        ho.x = h2u(o01);
        ho.y = h2u(o23);
        h16_out[v * DD + lane] = ho;
    }
}

// ---------------- final MLP scoring (reads fp16 hidden) ----------------
__global__ void __launch_bounds__(256) mlp_kernel(
    const uint2* __restrict__ hid16,
    const float* __restrict__ W1, const float* __restrict__ b1,
    const float* __restrict__ W2, const float* __restrict__ b2,
    float* __restrict__ out)
{
    __shared__ float  W1s[64 * 64];
    __shared__ float  W2s[64];
    __shared__ float  b1s[64];
    __shared__ float4 f2[NPB * 64];

    const int t = threadIdx.x;
    for (int i = t; i < 64 * 64; i += 256) W1s[i] = W1[i];
    if (t < 64) { W2s[t] = W2[t]; b1s[t] = b1[t]; }

    const int s = t >> 5, lane = t & 31;

    for (int it = 0; it < MLP_IT; ++it) {
        const int vbase = (blockIdx.x * MLP_IT + it) * NPB;
        if (vbase >= NN) break;
        __syncthreads();
        for (int i = t; i < NPB * 64; i += 256) {
            const int k = i & 63;
            const int sl = i >> 6;
            const int v = vbase + sl;
            float4 val = make_float4(0.f, 0.f, 0.f, 0.f);
            if (v < NN) val = (k < DD) ? cvt_rv(__ldg(&hid16[v * DD + k])) : g_qT[k - DD];
            f2[i] = val;
        }
        __syncthreads();

        const int v = vbase + s;
        if (v < NN) {
            ull a01 = dup2(b1s[lane]),      a23 = a01;
            ull b01 = dup2(b1s[lane + 32]), b23 = b01;
            const ulonglong2* up = (const ulonglong2*)&f2[s * 64];
#pragma unroll 8
            for (int k = 0; k < 64; ++k) {
                const ulonglong2 u = up[k];
                const ull wa = dup2(W1s[k * 64 + lane]);
                const ull wb = dup2(W1s[k * 64 + lane + 32]);
                a01 = fma2(u.x, wa, a01); a23 = fma2(u.y, wa, a23);
                b01 = fma2(u.x, wb, b01); b23 = fma2(u.y, wb, b23);
            }
            const float2 fa01 = unpk(a01), fa23 = unpk(a23);
            const float2 fb01 = unpk(b01), fb23 = unpk(b23);
            const float accA[4] = {fa01.x, fa01.y, fa23.x, fa23.y};
            const float accB[4] = {fb01.x, fb01.y, fb23.x, fb23.y};
            const float w2a = W2s[lane], w2b = W2s[lane + 32];
            const float bias2 = b2[0];
#pragma unroll
            for (int bb = 0; bb < 4; ++bb) {
                float p = fmaxf(accA[bb], 0.0f) * w2a + fmaxf(accB[bb], 0.0f) * w2b;
#pragma unroll
                for (int off = 16; off > 0; off >>= 1)
                    p += __shfl_down_sync(0xffffffffu, p, off);
                if (lane == 0) out[bb * NN + v] = p + bias2;
            }
        }
    }
}

// ---------------- launch ----------------
extern "C" void kernel_launch(void* const* d_in, const int* in_sizes, int n_in,
                              void* d_out, int out_size) {
    const int*   node_in     = (const int*)  d_in[0];
    const int*   node_out    = (const int*)  d_in[1];
    const int*   relation    = (const int*)  d_in[2];
    const float* edge_weight = (const float*)d_in[3];
    const int*   h_index     = (const int*)  d_in[4];
    const int*   r_index     = (const int*)  d_in[5];
    const float* query_embed = (const float*)d_in[6];
    const float* rel_W  = (const float*)d_in[7];
    const float* rel_b  = (const float*)d_in[8];
    const float* lin_W  = (const float*)d_in[9];
    const float* lin_b  = (const float*)d_in[10];
    const float* mlp_W1 = (const float*)d_in[11];
    const float* mlp_b1 = (const float*)d_in[12];
    const float* mlp_W2 = (const float*)d_in[13];
    const float* mlp_b2 = (const float*)d_in[14];
    float* out = (float*)d_out;

    uint2 *h16A, *h16B;
    cudaGetSymbolAddress((void**)&h16A, g_h16A);
    cudaGetSymbolAddress((void**)&h16B, g_h16B);

    setup_kernel<<<SB_TOTAL, 128>>>(h_index, r_index, query_embed,
                                    lin_W, rel_W, rel_b);       // 0
    hist_kernel<<<(NE + 255) / 256, 256>>>(node_out, edge_weight); // 1
    scan_kernel<<<SCAN_B, 1024>>>();                            // 2
    scatter_kernel<<<(NE + 255) / 256, 256>>>(node_in, node_out, relation, edge_weight); // 3

    const uint2* h16in = h16A;       // unused at layer 0
    uint2* h16outs[4] = {h16A, h16B, h16A, h16B};
    for (int l = 0; l < NL; ++l) {
        conv_kernel<<<NN / 4, 128>>>(lin_b, h16in, h16outs[l], h_index, l); // 4..7
        h16in = h16outs[l];
    }
    mlp_kernel<<<(NN + NPB * MLP_IT - 1) / (NPB * MLP_IT), 256>>>(
        h16in, mlp_W1, mlp_b1, mlp_W2, mlp_b2, out);            // 8
}

// round 15
// speedup vs baseline: 1.1831x; 1.0548x over previous
#include <cuda_runtime.h>
#include <cuda_fp16.h>
#include <math.h>
#include <stdint.h>

#define NN 25000
#define NE 500000
#define BQ 4
#define DD 32
#define RR 474
#define NL 4
#define KD 416          // 13*D
#define NSTEP 26        // KD/16 k-steps
#define EPSF 1e-6f
#define SCAN_B 25       // ceil(25000/1024)
#define MLP_IT2 2       // 32-node tiles per mlp block

// setup_kernel block partition
#define SB_RELIN (NL * RR)                 // 1896
#define SB_WSPLIT (SB_RELIN + NL * NSTEP)  // +104
#define SB_ZERO (SB_WSPLIT + 25)           // +25 (zero cnt/deg/flags)
#define SB_INIT (SB_ZERO + 1)              // +1 (init)
#define SB_TOTAL (SB_INIT + 1)             // +1 (W1 fragment split)

typedef unsigned long long ull;

// ---- packed fp32x2 helpers ----
__device__ __forceinline__ ull fma2(ull a, ull b, ull c) {
    ull d; asm("fma.rn.f32x2 %0,%1,%2,%3;" : "=l"(d) : "l"(a), "l"(b), "l"(c)); return d;
}
__device__ __forceinline__ ull add2(ull a, ull b) {
    ull d; asm("add.rn.f32x2 %0,%1,%2;" : "=l"(d) : "l"(a), "l"(b)); return d;
}
__device__ __forceinline__ ull pk2(float x, float y) {
    ull r; asm("mov.b64 %0,{%1,%2};" : "=l"(r) : "f"(x), "f"(y)); return r;
}
__device__ __forceinline__ float2 unpk(ull a) {
    float2 f; asm("mov.b64 {%0,%1},%2;" : "=f"(f.x), "=f"(f.y) : "l"(a)); return f;
}
__device__ __forceinline__ ull h2f2(__half2 h) {
    const float2 f = __half22float2(h);
    return pk2(f.x, f.y);
}
__device__ __forceinline__ __half2 u2h(uint32_t u) { return *(const __half2*)&u; }
__device__ __forceinline__ uint32_t h2u(__half2 h) { return *(const uint32_t*)&h; }
__device__ __forceinline__ float4 cvt_rv(const uint2 rh) {
    const float2 f01 = __half22float2(u2h(rh.x));
    const float2 f23 = __half22float2(u2h(rh.y));
    return make_float4(f01.x, f01.y, f23.x, f23.y);
}
// extract b-th fp16 component of a (b0,b1,b2,b3) uint2 as float
__device__ __forceinline__ float h16get(const uint2 e, int b) {
    const uint32_t u = (b < 2) ? e.x : e.y;
    const float2 f = __half22float2(u2h(u));
    return (b & 1) ? f.y : f.x;
}

// split (x0,x1) into bf16 hi pair + bf16 lo pair (lo = x - float(hi))
__device__ __forceinline__ void split2(float x0, float x1, uint32_t& h, uint32_t& l) {
    uint32_t hp; asm("cvt.rn.bf16x2.f32 %0,%1,%2;" : "=r"(hp) : "f"(x1), "f"(x0));
    const float l0 = x0 - __int_as_float(hp << 16);
    const float l1 = x1 - __int_as_float(hp & 0xFFFF0000u);
    uint32_t lp; asm("cvt.rn.bf16x2.f32 %0,%1,%2;" : "=r"(lp) : "f"(l1), "f"(l0));
    h = hp; l = lp;
}

__device__ __forceinline__ void mma16816(float& d0, float& d1, float& d2, float& d3,
                                         uint32_t a0, uint32_t a1, uint32_t a2, uint32_t a3,
                                         uint32_t b0, uint32_t b1) {
    asm volatile("mma.sync.aligned.m16n8k16.row.col.f32.bf16.bf16.f32 "
                 "{%0,%1,%2,%3},{%4,%5,%6,%7},{%8,%9},{%0,%1,%2,%3};"
                 : "+f"(d0), "+f"(d1), "+f"(d2), "+f"(d3)
                 : "r"(a0), "r"(a1), "r"(a2), "r"(a3), "r"(b0), "r"(b1));
}

// ---------------- scratch ----------------
__device__ int    g_cnt[NN];
__device__ float  g_deg[NN];
__device__ int    g_rowptr[NN + 1];
__device__ int    g_pos[NN];
__device__ int2   g_epack[NE];          // CSR-ordered (nin | rel<<16, w_bits)
__device__ float2 g_sc[NN];             // (s1, s2)
__device__ int    g_flag[SCAN_B];
__device__ int    g_partI[SCAN_B];
__device__ float  g_partF[SCAN_B];
__device__ uint2  g_h16A[NN * DD];      // fp16x2 hidden state
__device__ uint2  g_h16B[NN * DD];
__device__ uint2  g_relinH[NL * RR * DD]; // fp16x2 pairs: (b0,b1),(b2,b3)
__device__ float4 g_qT[DD];             // [d] -> b-vector
__device__ float  g_csum[3 * DD];       // layer-0 std-column sums per scale
__device__ uint4  g_Wmma[NL * NSTEP * 128]; // fragment-ordered split conv weights
__device__ uint4  g_W1mma[32 * 32];     // fragment-ordered split mlp W1 [(s*8+j)*32+lane]

// ---------------- fused setup (input-only work, launch #0) ----------------
__global__ void __launch_bounds__(128) setup_kernel(
    const int* __restrict__ h_index,
    const int* __restrict__ r_index,
    const float* __restrict__ query_embed,
    const float* __restrict__ lin_W,
    const float* __restrict__ rel_W,
    const float* __restrict__ rel_b,
    const float* __restrict__ mlp_W1)
{
    const int bx = blockIdx.x;
    const int t = threadIdx.x;

    if (bx < SB_RELIN) {
        __shared__ float acc_s[BQ][DD];
        const int l = bx / RR, r = bx - l * RR;
        const int d = t & 31, b = t >> 5;
        const int ri = __ldg(&r_index[b]);
        const float* W = rel_W + (size_t)l * DD * RR * DD + (size_t)r * DD + d;
        float acc = rel_b[(size_t)l * RR * DD + r * DD + d];
#pragma unroll
        for (int k = 0; k < DD; ++k)
            acc += __ldg(&query_embed[ri * DD + k]) * W[(size_t)k * RR * DD];
        acc_s[b][d] = acc;
        __syncthreads();
        if (t < DD) {
            const __half2 p01 = __floats2half2_rn(acc_s[0][t], acc_s[1][t]);
            const __half2 p23 = __floats2half2_rn(acc_s[2][t], acc_s[3][t]);
            uint2 o;
            o.x = h2u(p01);
            o.y = h2u(p23);
            g_relinH[(size_t)(l * RR + r) * DD + t] = o;
        }
    } else if (bx < SB_WSPLIT) {
        const int i = bx - SB_RELIN;
        const int l = i / NSTEP, s = i % NSTEP;
        const int w = t >> 5, lane = t & 31;
        const int c = lane & 3, n = 8 * w + (lane >> 2);
        const int k0 = 16 * s;
        const float* W = lin_W + (size_t)l * KD * DD;
        const float w00 = W[(k0 + 2 * c) * DD + n];
        const float w01 = W[(k0 + 2 * c + 1) * DD + n];
        const float w10 = W[(k0 + 8 + 2 * c) * DD + n];
        const float w11 = W[(k0 + 9 + 2 * c) * DD + n];
        uint32_t h0, l0, h1, l1;
        split2(w00, w01, h0, l0);
        split2(w10, w11, h1, l1);
        g_Wmma[(size_t)(l * NSTEP + s) * 128 + t] = make_uint4(h0, h1, l0, l1);
    } else if (bx < SB_ZERO) {
        const int bi = bx - SB_WSPLIT;
        const int base = bi * 1000;
        for (int i = base + t; i < base + 1000 && i < NN; i += 128) {
            g_cnt[i] = 0;
            g_deg[i] = 0.0f;
        }
        if (bi == 0 && t < SCAN_B) g_flag[t] = 0;
    } else if (bx < SB_INIT) {
        if (t < 128) {
            const int b = t >> 5, d = t & 31;
            ((float*)g_qT)[d * 4 + b] = __ldg(&query_embed[__ldg(&r_index[b]) * DD + d]);
        }
        __syncthreads();
        if (t < DD) {
            const int j = t;
#pragma unroll
            for (int s = 0; s < 3; ++s) {
                float c = 0.0f;
#pragma unroll
                for (int dd = 0; dd < DD; ++dd)
                    c += lin_W[(DD + (4 * dd + 3) * 3 + s) * DD + j];
                g_csum[s * DD + j] = c;
            }
        }
    } else {
        // mlp W1 [64x64] -> fragment-ordered bf16 hi/lo (same scheme as conv)
        const int lane = t & 31, jj = t >> 5;  // jj = 0..3
        const int c = lane & 3, gq = lane >> 2;
#pragma unroll
        for (int jo = 0; jo < 2; ++jo) {
            const int j = jj + 4 * jo;
            const int n = 8 * j + gq;
#pragma unroll
            for (int s = 0; s < 4; ++s) {
                const int k0 = 16 * s;
                const float w00 = mlp_W1[(k0 + 2 * c) * 64 + n];
                const float w01 = mlp_W1[(k0 + 2 * c + 1) * 64 + n];
                const float w10 = mlp_W1[(k0 + 8 + 2 * c) * 64 + n];
                const float w11 = mlp_W1[(k0 + 9 + 2 * c) * 64 + n];
                uint32_t h0, l0, h1, l1;
                split2(w00, w01, h0, l0);
                split2(w10, w11, h1, l1);
                g_W1mma[(s * 8 + j) * 32 + lane] = make_uint4(h0, h1, l0, l1);
            }
        }
    }
}

// ---------------- graph-build kernels ----------------
__global__ void hist_kernel(const int* __restrict__ node_out,
                            const float* __restrict__ ew) {
    const int e = blockIdx.x * 256 + threadIdx.x;
    if (e < NE) {
        const int v = node_out[e];
        atomicAdd(&g_cnt[v], 1);
        atomicAdd(&g_deg[v], ew[e]);
    }
}

// single-kernel decoupled scan
__global__ void __launch_bounds__(1024) scan_kernel() {
    __shared__ int wsum[32];
    __shared__ int woff[32];
    __shared__ float lsum[32];
    __shared__ int sI[SCAN_B];
    __shared__ float sF[SCAN_B];
    const int t = threadIdx.x, wid = t >> 5, lane = t & 31;
    const int b = blockIdx.x;
    const int i = b * 1024 + t;
    const int x = (i < NN) ? g_cnt[i] : 0;
    float y = (i < NN) ? logf(g_deg[i] + 1.0f) : 0.0f;

    int incl = x;
#pragma unroll
    for (int off = 1; off < 32; off <<= 1) {
        int n = __shfl_up_sync(0xffffffffu, incl, off);
        if (lane >= off) incl += n;
    }
#pragma unroll
    for (int off = 16; off > 0; off >>= 1)
        y += __shfl_down_sync(0xffffffffu, y, off);
    if (lane == 31) wsum[wid] = incl;
    if (lane == 0)  lsum[wid] = y;
    __syncthreads();
    if (wid == 0) {
        int s = wsum[lane];
        int si = s;
#pragma unroll
        for (int off = 1; off < 32; off <<= 1) {
            int n = __shfl_up_sync(0xffffffffu, si, off);
            if (lane >= off) si += n;
        }
        woff[lane] = si - s;
        if (lane == 31) g_partI[b] = si;
    }
    __syncthreads();
    if (t == 0) {
        float ftot = 0.0f;
#pragma unroll
        for (int ww = 0; ww < 32; ++ww) ftot += lsum[ww];
        g_partF[b] = ftot;
        __threadfence();
        atomicExch(&g_flag[b], 1);
    }
    if (t < SCAN_B) {
        while (atomicAdd(&g_flag[t], 0) == 0) {}
        sI[t] = g_partI[t];
        sF[t] = g_partF[t];
    }
    __syncthreads();
    int off = 0;
    float gl = 0.0f;
#pragma unroll
    for (int j = 0; j < SCAN_B; ++j) {
        if (j < b) off += sI[j];
        gl += sF[j];
    }
    if (i < NN) {
        const int rp = incl - x + woff[wid] + off;
        g_rowptr[i] = rp;
        g_pos[i] = rp;
        const float mean = gl / (float)NN;
        const float s = logf(g_deg[i] + 1.0f) / mean;
        g_sc[i] = make_float2(s, 1.0f / fmaxf(s, 0.01f));
    }
    if (i == 0) g_rowptr[NN] = NE;
}

__global__ void scatter_kernel(const int* __restrict__ node_in,
                               const int* __restrict__ node_out,
                               const int* __restrict__ relation,
                               const float* __restrict__ ew) {
    const int e = blockIdx.x * 256 + threadIdx.x;
    if (e < NE) {
        const int p = atomicAdd(&g_pos[node_out[e]], 1);
        g_epack[p] = make_int2(node_in[e] | (relation[e] << 16),
                               __float_as_int(ew[e]));
    }
}

// ---------------- fused conv layer (R12-proven structure) ----------------
__device__ __forceinline__ uint2 ldcg2u(const uint2* p) {
    uint2 v;
    asm volatile("ld.global.cg.v2.u32 {%0,%1},[%2];"
                 : "=r"(v.x), "=r"(v.y) : "l"(p));
    return v;
}

#define WRITE_PAIR(p, x0, x1)                                              \
    do {                                                                   \
        uint32_t hh_, ll_;                                                 \
        split2((x0).x, (x1).x, hh_, ll_);                                  \
        catH[p][r0] = hh_; catL[p][r0] = ll_;                              \
        split2((x0).y, (x1).y, hh_, ll_);                                  \
        catH[p][r0 + 1] = hh_; catL[p][r0 + 1] = ll_;                      \
        split2((x0).z, (x1).z, hh_, ll_);                                  \
        catH[p][r0 + 2] = hh_; catL[p][r0 + 2] = ll_;                      \
        split2((x0).w, (x1).w, hh_, ll_);                                  \
        catH[p][r0 + 3] = hh_; catL[p][r0 + 3] = ll_;                      \
    } while (0)

#define EDGE_CORE(rv_, hh_, wbits_, mw01o, mw23o)                          \
    do {                                                                   \
        const __half2 wh_ = __float2half2_rn(__int_as_float(wbits_));      \
        const __half2 m01_ = __hmul2(u2h((rv_).x), u2h((hh_).x));          \
        const __half2 m23_ = __hmul2(u2h((rv_).y), u2h((hh_).y));          \
        mw01o = __hmul2(m01_, wh_);                                        \
        mw23o = __hmul2(m23_, wh_);                                        \
        mxh01 = __hmax2(mxh01, mw01o); mxh23 = __hmax2(mxh23, mw23o);      \
        mnh01 = __hmin2(mnh01, mw01o); mnh23 = __hmin2(mnh23, mw23o);      \
        sqh01 = __hfma2(m01_, mw01o, sqh01);                               \
        sqh23 = __hfma2(m23_, mw23o, sqh23);                               \
    } while (0)

__global__ void __launch_bounds__(128) conv_kernel(
    const float* __restrict__ lin_b,
    const uint2* __restrict__ h16_in, uint2* __restrict__ h16_out,
    const int* __restrict__ h_index, int layer)
{
    __shared__ uint32_t catH[KD / 2][17];
    __shared__ uint32_t catL[KD / 2][17];
    __shared__ int s_act[4];
    __shared__ float2 s_scl[4];
    float* sD = (float*)catL;

    const int t = threadIdx.x, w = t >> 5, lane = t & 31;
    const int v = blockIdx.x * 4 + w;
    const int d = lane;
    const uint2* relin = g_relinH + (size_t)layer * RR * DD + d;

    // ---- message phase (warp per node) ----
    {
        const int4 h = *(const int4*)h_index;
        const float4 q = g_qT[d];
        const float4 m0 = make_float4(v == h.x ? q.x : 0.f,
                                      v == h.y ? q.y : 0.f,
                                      v == h.z ? q.z : 0.f,
                                      v == h.w ? q.w : 0.f);
        int p = g_rowptr[v];
        const int e_ = g_rowptr[v + 1];
        const int degv = e_ - p;
        int act;
        float4 hv;
        float4 sumF, sqF, mxF, mnF;

        if (layer == 0) {
            hv = m0;
            float4 sum = m0, mx = m0, mn = m0;
            float4 sq = make_float4(m0.x * m0.x, m0.y * m0.y, m0.z * m0.z, m0.w * m0.w);
            act = (v == h.x) | (v == h.y) | (v == h.z) | (v == h.w);
            int nacc = 0;
            for (; p < e_; ++p) {
                const int2 ep = __ldg(&g_epack[p]);
                const int nin = ep.x & 0xFFFF;
                if (nin == h.x || nin == h.y || nin == h.z || nin == h.w) {
                    act = 1; ++nacc;
                    const uint2 rvh = __ldg(&relin[(ep.x >> 16) * DD]);
                    const float2 r01 = __half22float2(u2h(rvh.x));
                    const float2 r23 = __half22float2(u2h(rvh.y));
                    const float4 hh = make_float4(nin == h.x ? q.x : 0.f,
                                                  nin == h.y ? q.y : 0.f,
                                                  nin == h.z ? q.z : 0.f,
                                                  nin == h.w ? q.w : 0.f);
                    const float wgt = __int_as_float(ep.y);
                    float m, mw;
                    m = r01.x * hh.x; mw = m * wgt; sum.x += mw; sq.x = fmaf(m, mw, sq.x); mx.x = fmaxf(mx.x, mw); mn.x = fminf(mn.x, mw);
                    m = r01.y * hh.y; mw = m * wgt; sum.y += mw; sq.y = fmaf(m, mw, sq.y); mx.y = fmaxf(mx.y, mw); mn.y = fminf(mn.y, mw);
                    m = r23.x * hh.z; mw = m * wgt; sum.z += mw; sq.z = fmaf(m, mw, sq.z); mx.z = fmaxf(mx.z, mw); mn.z = fminf(mn.z, mw);
                    m = r23.y * hh.w; mw = m * wgt; sum.w += mw; sq.w = fmaf(m, mw, sq.w); mx.w = fmaxf(mx.w, mw); mn.w = fminf(mn.w, mw);
                }
            }
            if (nacc < degv) {
                mx.x = fmaxf(mx.x, 0.f); mx.y = fmaxf(mx.y, 0.f); mx.z = fmaxf(mx.z, 0.f); mx.w = fmaxf(mx.w, 0.f);
                mn.x = fminf(mn.x, 0.f); mn.y = fminf(mn.y, 0.f); mn.z = fminf(mn.z, 0.f); mn.w = fminf(mn.w, 0.f);
            }
            sumF = sum; sqF = sq; mxF = mx; mnF = mn;
        } else {
            act = 1;
            hv = cvt_rv(__ldg(&h16_in[v * DD + d]));
            ull sum01 = pk2(m0.x, m0.y), sum23 = pk2(m0.z, m0.w);
            __half2 sqh01 = __floats2half2_rn(m0.x * m0.x, m0.y * m0.y);
            __half2 sqh23 = __floats2half2_rn(m0.z * m0.z, m0.w * m0.w);
            __half2 mxh01 = __floats2half2_rn(m0.x, m0.y);
            __half2 mxh23 = __floats2half2_rn(m0.z, m0.w);
            __half2 mnh01 = mxh01, mnh23 = mxh23;

            const int nfull = (e_ - p) >> 2;
            if (nfull > 0) {
                int2 ee[4];
#pragma unroll
                for (int j = 0; j < 4; ++j) ee[j] = __ldg(&g_epack[p + j]);
                for (int b = 0; b < nfull; ++b) {
                    uint2 rv[4], hh[4];
#pragma unroll
                    for (int j = 0; j < 4; ++j) {
                        rv[j] = __ldg(&relin[(ee[j].x >> 16) * DD]);
                        hh[j] = ldcg2u(&h16_in[(ee[j].x & 0xFFFF) * DD + d]);
                    }
                    const int wb0 = ee[0].y, wb1 = ee[1].y;
                    const int wb2 = ee[2].y, wb3 = ee[3].y;
                    if (b + 1 < nfull) {
                        const int pn = p + 4 * (b + 1);
#pragma unroll
                        for (int j = 0; j < 4; ++j) ee[j] = __ldg(&g_epack[pn + j]);
                    }
                    __half2 a01, a23, b01, b23, c01, c23, d01, d23;
                    EDGE_CORE(rv[0], hh[0], wb0, a01, a23);
                    EDGE_CORE(rv[1], hh[1], wb1, b01, b23);
                    EDGE_CORE(rv[2], hh[2], wb2, c01, c23);
                    EDGE_CORE(rv[3], hh[3], wb3, d01, d23);
                    const __half2 t01 = __hadd2(__hadd2(a01, b01), __hadd2(c01, d01));
                    const __half2 t23 = __hadd2(__hadd2(a23, b23), __hadd2(c23, d23));
                    sum01 = add2(sum01, h2f2(t01));
                    sum23 = add2(sum23, h2f2(t23));
                }
                p += nfull * 4;
            }
            for (; p < e_; ++p) {
                const int2 e0 = __ldg(&g_epack[p]);
                const uint2 rv0 = __ldg(&relin[(e0.x >> 16) * DD]);
                const uint2 hh0 = ldcg2u(&h16_in[(e0.x & 0xFFFF) * DD + d]);
                __half2 a01, a23;
                EDGE_CORE(rv0, hh0, e0.y, a01, a23);
                sum01 = add2(sum01, h2f2(a01));
                sum23 = add2(sum23, h2f2(a23));
            }
            const float2 s01 = unpk(sum01), s23 = unpk(sum23);
            const float2 q01 = __half22float2(sqh01), q23 = __half22float2(sqh23);
            const float2 x01 = __half22float2(mxh01), x23 = __half22float2(mxh23);
            const float2 n01 = __half22float2(mnh01), n23 = __half22float2(mnh23);
            sumF = make_float4(s01.x, s01.y, s23.x, s23.y);
            sqF  = make_float4(q01.x, q01.y, q23.x, q23.y);
            mxF  = make_float4(x01.x, x01.y, x23.x, x23.y);
            mnF  = make_float4(n01.x, n01.y, n23.x, n23.y);
        }

        if (lane == 0) { s_act[w] = act; s_scl[w] = g_sc[v]; }

        if (act) {
            const float inv = 1.0f / (float)(degv + 1);
            float4 mean, var, sd2;
            mean.x = sumF.x * inv; mean.y = sumF.y * inv; mean.z = sumF.z * inv; mean.w = sumF.w * inv;
            var.x = sqF.x * inv - mean.x * mean.x; var.y = sqF.y * inv - mean.y * mean.y;
            var.z = sqF.z * inv - mean.z * mean.z; var.w = sqF.w * inv - mean.w * mean.w;
            sd2.x = sqrtf(fmaxf(var.x, EPSF)); sd2.y = sqrtf(fmaxf(var.y, EPSF));
            sd2.z = sqrtf(fmaxf(var.z, EPSF)); sd2.w = sqrtf(fmaxf(var.w, EPSF));
            const float2 sc = g_sc[v];
            const int r0 = w * 4;

            float4 hv1;
            hv1.x = __shfl_down_sync(0xffffffffu, hv.x, 1);
            hv1.y = __shfl_down_sync(0xffffffffu, hv.y, 1);
            hv1.z = __shfl_down_sync(0xffffffffu, hv.z, 1);
            hv1.w = __shfl_down_sync(0xffffffffu, hv.w, 1);
            if ((d & 1) == 0) WRITE_PAIR(d >> 1, hv, hv1);

            float4 f[12];
            const float4 st4[4] = {mean, mxF, mnF, sd2};
#pragma unroll
            for (int si = 0; si < 4; ++si) {
                const float4 fv = st4[si];
                f[si * 3 + 0] = fv;
                f[si * 3 + 1] = make_float4(fv.x * sc.x, fv.y * sc.x, fv.z * sc.x, fv.w * sc.x);
                f[si * 3 + 2] = make_float4(fv.x * sc.y, fv.y * sc.y, fv.z * sc.y, fv.w * sc.y);
            }
            const int pb = 16 + 6 * d;
#pragma unroll
            for (int pi = 0; pi < 6; ++pi)
                WRITE_PAIR(pb + pi, f[2 * pi], f[2 * pi + 1]);
        }
    }
    __syncthreads();

    const int anyact = s_act[0] | s_act[1] | s_act[2] | s_act[3];

    // ---- GEMM via mma.sync bf16 3-split ----
    float d0 = 0.f, d1 = 0.f, d2 = 0.f, d3 = 0.f;
    const int c = lane & 3, g = lane >> 2;
    if (anyact) {
        const uint4* Wp = g_Wmma + (size_t)layer * NSTEP * 128 + (w * 32 + lane);
#pragma unroll
        for (int s = 0; s < NSTEP; ++s) {
            const uint4 wv = __ldg(&Wp[(size_t)s * 128]);
            const int pA = s * 8 + c, pB = s * 8 + 4 + c;
            const uint32_t ah0 = catH[pA][g], ah1 = catH[pA][g + 8];
            const uint32_t ah2 = catH[pB][g], ah3 = catH[pB][g + 8];
            const uint32_t al0 = catL[pA][g], al1 = catL[pA][g + 8];
            const uint32_t al2 = catL[pB][g], al3 = catL[pB][g + 8];
            mma16816(d0, d1, d2, d3, ah0, ah1, ah2, ah3, wv.x, wv.y);
            mma16816(d0, d1, d2, d3, ah0, ah1, ah2, ah3, wv.z, wv.w);
            mma16816(d0, d1, d2, d3, al0, al1, al2, al3, wv.x, wv.y);
        }
    }
    __syncthreads();
    if (anyact) {
        const int j0 = 8 * w + 2 * c;
        sD[g * 33 + j0] = d0;       sD[g * 33 + j0 + 1] = d1;
        sD[(g + 8) * 33 + j0] = d2; sD[(g + 8) * 33 + j0 + 1] = d3;
    }
    __syncthreads();

    // ---- epilogue: fp16 hidden only ----
    {
        const float bias = lin_b[layer * DD + lane];
        float4 o;
        if (s_act[w]) {
            o = make_float4(fmaxf(sD[(w * 4 + 0) * 33 + lane] + bias, 0.0f),
                            fmaxf(sD[(w * 4 + 1) * 33 + lane] + bias, 0.0f),
                            fmaxf(sD[(w * 4 + 2) * 33 + lane] + bias, 0.0f),
                            fmaxf(sD[(w * 4 + 3) * 33 + lane] + bias, 0.0f));
        } else {
            const float sd = sqrtf(EPSF);
            const float2 sc = s_scl[w];
            const float c2 = g_csum[lane] + sc.x * g_csum[DD + lane] + sc.y * g_csum[2 * DD + lane];
            const float val = fmaxf(bias + sd * c2, 0.0f);
            o = make_float4(val, val, val, val);
        }
        const __half2 o01 = __floats2half2_rn(o.x, o.y);
        const __half2 o23 = __floats2half2_rn(o.z, o.w);
        uint2 ho;
        ho.x = h2u(o01);
        ho.y = h2u(o23);
        h16_out[v * DD + lane] = ho;
    }
}

// ---------------- final MLP scoring via mma (block = 32 nodes / iter) ----------------
__global__ void __launch_bounds__(256) mlp_kernel(
    const uint2* __restrict__ hid16,
    const float* __restrict__ b1,
    const float* __restrict__ W2, const float* __restrict__ b2,
    float* __restrict__ out)
{
    __shared__ uint32_t fAH[32][132];   // [k-pair][row 0..127] 16.5KB
    __shared__ uint32_t fAL[32][132];   // 16.5KB
    __shared__ float b1s[64];
    __shared__ float W2s[64];

    const int t = threadIdx.x, w = t >> 5, lane = t & 31;
    const int c = lane & 3, g = lane >> 2;
    if (t < 64) { b1s[t] = b1[t]; W2s[t] = W2[t]; }

    for (int it = 0; it < MLP_IT2; ++it) {
        const int vbase = (blockIdx.x * MLP_IT2 + it) * 32;
        __syncthreads();
        // fill A fragments: thread -> (row r = t>>1, half = t&1)
        {
            const int r = t >> 1, half = t & 1;
            const int v = vbase + (r >> 2), b = r & 3;
            if (half == 0) {
                const uint2* hp = hid16 + (size_t)v * DD;
#pragma unroll
                for (int kp = 0; kp < 16; ++kp) {
                    float x0 = 0.f, x1 = 0.f;
                    if (v < NN) {
                        x0 = h16get(__ldg(&hp[2 * kp]), b);
                        x1 = h16get(__ldg(&hp[2 * kp + 1]), b);
                    }
                    uint32_t hh, ll;
                    split2(x0, x1, hh, ll);
                    fAH[kp][r] = hh; fAL[kp][r] = ll;
                }
            } else {
#pragma unroll
                for (int kp = 0; kp < 16; ++kp) {
                    const float4 q0 = g_qT[2 * kp];
                    const float4 q1 = g_qT[2 * kp + 1];
                    const float x0 = (b == 0) ? q0.x : (b == 1) ? q0.y : (b == 2) ? q0.z : q0.w;
                    const float x1 = (b == 0) ? q1.x : (b == 1) ? q1.y : (b == 2) ? q1.z : q1.w;
                    uint32_t hh, ll;
                    split2(x0, x1, hh, ll);
                    fAH[16 + kp][r] = hh; fAL[16 + kp][r] = ll;
                }
            }
        }
        __syncthreads();

        // GEMM: warp w handles rows [16w, 16w+16)
        const int base = w * 16;
        float sLo = 0.f, sHi = 0.f;
#pragma unroll
        for (int j = 0; j < 8; ++j) {
            float d0 = 0.f, d1 = 0.f, d2 = 0.f, d3 = 0.f;
#pragma unroll
            for (int s = 0; s < 4; ++s) {
                const uint4 wv = __ldg(&g_W1mma[(s * 8 + j) * 32 + lane]);
                const int pA = s * 8 + c, pB = pA + 4;
                const uint32_t ah0 = fAH[pA][base + g], ah1 = fAH[pA][base + g + 8];
                const uint32_t ah2 = fAH[pB][base + g], ah3 = fAH[pB][base + g + 8];
                const uint32_t al0 = fAL[pA][base + g], al1 = fAL[pA][base + g + 8];
                const uint32_t al2 = fAL[pB][base + g], al3 = fAL[pB][base + g + 8];
                mma16816(d0, d1, d2, d3, ah0, ah1, ah2, ah3, wv.x, wv.y);
                mma16816(d0, d1, d2, d3, ah0, ah1, ah2, ah3, wv.z, wv.w);
                mma16816(d0, d1, d2, d3, al0, al1, al2, al3, wv.x, wv.y);
            }
            const int n0 = 8 * j + 2 * c, n1 = n0 + 1;
            sLo += fmaxf(d0 + b1s[n0], 0.0f) * W2s[n0] + fmaxf(d1 + b1s[n1], 0.0f) * W2s[n1];
            sHi += fmaxf(d2 + b1s[n0], 0.0f) * W2s[n0] + fmaxf(d3 + b1s[n1], 0.0f) * W2s[n1];
        }
        // reduce over the 4 lanes sharing a row (c dimension)
        sLo += __shfl_xor_sync(0xffffffffu, sLo, 1);
        sLo += __shfl_xor_sync(0xffffffffu, sLo, 2);
        sHi += __shfl_xor_sync(0xffffffffu, sHi, 1);
        sHi += __shfl_xor_sync(0xffffffffu, sHi, 2);
        if (c == 0) {
            const float bias2 = __ldg(&b2[0]);
            const int R0 = base + g;
            const int v0 = vbase + (R0 >> 2), b0 = R0 & 3;
            if (v0 < NN) out[b0 * NN + v0] = sLo + bias2;
            const int R1 = base + g + 8;
            const int v1 = vbase + (R1 >> 2), bb1 = R1 & 3;
            if (v1 < NN) out[bb1 * NN + v1] = sHi + bias2;
        }
    }
}

// ---------------- launch ----------------
extern "C" void kernel_launch(void* const* d_in, const int* in_sizes, int n_in,
                              void* d_out, int out_size) {
    const int*   node_in     = (const int*)  d_in[0];
    const int*   node_out    = (const int*)  d_in[1];
    const int*   relation    = (const int*)  d_in[2];
    const float* edge_weight = (const float*)d_in[3];
    const int*   h_index     = (const int*)  d_in[4];
    const int*   r_index     = (const int*)  d_in[5];
    const float* query_embed = (const float*)d_in[6];
    const float* rel_W  = (const float*)d_in[7];
    const float* rel_b  = (const float*)d_in[8];
    const float* lin_W  = (const float*)d_in[9];
    const float* lin_b  = (const float*)d_in[10];
    const float* mlp_W1 = (const float*)d_in[11];
    const float* mlp_b1 = (const float*)d_in[12];
    const float* mlp_W2 = (const float*)d_in[13];
    const float* mlp_b2 = (const float*)d_in[14];
    float* out = (float*)d_out;

    uint2 *h16A, *h16B;
    cudaGetSymbolAddress((void**)&h16A, g_h16A);
    cudaGetSymbolAddress((void**)&h16B, g_h16B);

    setup_kernel<<<SB_TOTAL, 128>>>(h_index, r_index, query_embed,
                                    lin_W, rel_W, rel_b, mlp_W1);  // 0
    hist_kernel<<<(NE + 255) / 256, 256>>>(node_out, edge_weight); // 1
    scan_kernel<<<SCAN_B, 1024>>>();                               // 2
    scatter_kernel<<<(NE + 255) / 256, 256>>>(node_in, node_out, relation, edge_weight); // 3

    const uint2* h16in = h16A;       // unused at layer 0
    uint2* h16outs[4] = {h16A, h16B, h16A, h16B};
    for (int l = 0; l < NL; ++l) {
        conv_kernel<<<NN / 4, 128>>>(lin_b, h16in, h16outs[l], h_index, l); // 4..7
        h16in = h16outs[l];
    }
    mlp_kernel<<<(NN + 32 * MLP_IT2 - 1) / (32 * MLP_IT2), 256>>>(
        h16in, mlp_b1, mlp_W2, mlp_b2, out);                       // 8
}

// round 16
// speedup vs baseline: 1.2168x; 1.0285x over previous
#include <cuda_runtime.h>
#include <cuda_fp16.h>
#include <math.h>
#include <stdint.h>

#define NN 25000
#define NE 500000
#define BQ 4
#define DD 32
#define RR 474
#define NL 4
#define KD 416          // 13*D
#define NSTEP 26        // KD/16 k-steps
#define EPSF 1e-6f
#define SCAN_B 25       // ceil(25000/1024)
#define MLP_IT2 2       // 32-node tiles per mlp block
#define NMASK ((NN + 31) / 32)

// setup_kernel block partition
#define SB_RELIN (NL * RR)                 // 1896
#define SB_WSPLIT (SB_RELIN + NL * NSTEP)  // +104
#define SB_ZERO (SB_WSPLIT + 25)           // +25 (zero cnt/deg/flags/mask)
#define SB_INIT (SB_ZERO + 1)              // +1 (init)
#define SB_TOTAL (SB_INIT + 1)             // +1 (W1 fragment split)

typedef unsigned long long ull;

// ---- packed fp32x2 helpers ----
__device__ __forceinline__ ull fma2(ull a, ull b, ull c) {
    ull d; asm("fma.rn.f32x2 %0,%1,%2,%3;" : "=l"(d) : "l"(a), "l"(b), "l"(c)); return d;
}
__device__ __forceinline__ ull add2(ull a, ull b) {
    ull d; asm("add.rn.f32x2 %0,%1,%2;" : "=l"(d) : "l"(a), "l"(b)); return d;
}
__device__ __forceinline__ ull pk2(float x, float y) {
    ull r; asm("mov.b64 %0,{%1,%2};" : "=l"(r) : "f"(x), "f"(y)); return r;
}
__device__ __forceinline__ float2 unpk(ull a) {
    float2 f; asm("mov.b64 {%0,%1},%2;" : "=f"(f.x), "=f"(f.y) : "l"(a)); return f;
}
__device__ __forceinline__ ull h2f2(__half2 h) {
    const float2 f = __half22float2(h);
    return pk2(f.x, f.y);
}
__device__ __forceinline__ __half2 u2h(uint32_t u) { return *(const __half2*)&u; }
__device__ __forceinline__ uint32_t h2u(__half2 h) { return *(const uint32_t*)&h; }
__device__ __forceinline__ float4 cvt_rv(const uint2 rh) {
    const float2 f01 = __half22float2(u2h(rh.x));
    const float2 f23 = __half22float2(u2h(rh.y));
    return make_float4(f01.x, f01.y, f23.x, f23.y);
}
// extract b-th fp16 component of a (b0,b1,b2,b3) uint2 as float
__device__ __forceinline__ float h16get(const uint2 e, int b) {
    const uint32_t u = (b < 2) ? e.x : e.y;
    const float2 f = __half22float2(u2h(u));
    return (b & 1) ? f.y : f.x;
}

// split (x0,x1) into bf16 hi pair + bf16 lo pair (lo = x - float(hi))
__device__ __forceinline__ void split2(float x0, float x1, uint32_t& h, uint32_t& l) {
    uint32_t hp; asm("cvt.rn.bf16x2.f32 %0,%1,%2;" : "=r"(hp) : "f"(x1), "f"(x0));
    const float l0 = x0 - __int_as_float(hp << 16);
    const float l1 = x1 - __int_as_float(hp & 0xFFFF0000u);
    uint32_t lp; asm("cvt.rn.bf16x2.f32 %0,%1,%2;" : "=r"(lp) : "f"(l1), "f"(l0));
    h = hp; l = lp;
}

__device__ __forceinline__ void mma16816(float& d0, float& d1, float& d2, float& d3,
                                         uint32_t a0, uint32_t a1, uint32_t a2, uint32_t a3,
                                         uint32_t b0, uint32_t b1) {
    asm volatile("mma.sync.aligned.m16n8k16.row.col.f32.bf16.bf16.f32 "
                 "{%0,%1,%2,%3},{%4,%5,%6,%7},{%8,%9},{%0,%1,%2,%3};"
                 : "+f"(d0), "+f"(d1), "+f"(d2), "+f"(d3)
                 : "r"(a0), "r"(a1), "r"(a2), "r"(a3), "r"(b0), "r"(b1));
}

// ---------------- scratch ----------------
__device__ int    g_cnt[NN];
__device__ float  g_deg[NN];
__device__ int    g_rowptr[NN + 1];
__device__ int    g_pos[NN];
__device__ int2   g_epack[NE];          // CSR-ordered (nin | rel<<16, w_bits)
__device__ float2 g_sc[NN];             // (s1, s2)
__device__ int    g_flag[SCAN_B];
__device__ int    g_partI[SCAN_B];
__device__ float  g_partF[SCAN_B];
__device__ unsigned g_actmask[NMASK];   // layer-0: dst nodes of head-source edges
__device__ uint2  g_h16A[NN * DD];      // fp16x2 hidden state
__device__ uint2  g_h16B[NN * DD];
__device__ uint2  g_relinH[NL * RR * DD]; // fp16x2 pairs: (b0,b1),(b2,b3)
__device__ float4 g_qT[DD];             // [d] -> b-vector
__device__ float  g_csum[3 * DD];       // layer-0 std-column sums per scale
__device__ uint4  g_Wmma[NL * NSTEP * 128]; // fragment-ordered split conv weights
__device__ uint4  g_W1mma[32 * 32];     // fragment-ordered split mlp W1

// ---------------- fused setup (input-only work, launch #0) ----------------
__global__ void __launch_bounds__(128) setup_kernel(
    const int* __restrict__ h_index,
    const int* __restrict__ r_index,
    const float* __restrict__ query_embed,
    const float* __restrict__ lin_W,
    const float* __restrict__ rel_W,
    const float* __restrict__ rel_b,
    const float* __restrict__ mlp_W1)
{
    const int bx = blockIdx.x;
    const int t = threadIdx.x;

    if (bx < SB_RELIN) {
        __shared__ float acc_s[BQ][DD];
        const int l = bx / RR, r = bx - l * RR;
        const int d = t & 31, b = t >> 5;
        const int ri = __ldg(&r_index[b]);
        const float* W = rel_W + (size_t)l * DD * RR * DD + (size_t)r * DD + d;
        float acc = rel_b[(size_t)l * RR * DD + r * DD + d];
#pragma unroll
        for (int k = 0; k < DD; ++k)
            acc += __ldg(&query_embed[ri * DD + k]) * W[(size_t)k * RR * DD];
        acc_s[b][d] = acc;
        __syncthreads();
        if (t < DD) {
            const __half2 p01 = __floats2half2_rn(acc_s[0][t], acc_s[1][t]);
            const __half2 p23 = __floats2half2_rn(acc_s[2][t], acc_s[3][t]);
            uint2 o;
            o.x = h2u(p01);
            o.y = h2u(p23);
            g_relinH[(size_t)(l * RR + r) * DD + t] = o;
        }
    } else if (bx < SB_WSPLIT) {
        const int i = bx - SB_RELIN;
        const int l = i / NSTEP, s = i % NSTEP;
        const int w = t >> 5, lane = t & 31;
        const int c = lane & 3, n = 8 * w + (lane >> 2);
        const int k0 = 16 * s;
        const float* W = lin_W + (size_t)l * KD * DD;
        const float w00 = W[(k0 + 2 * c) * DD + n];
        const float w01 = W[(k0 + 2 * c + 1) * DD + n];
        const float w10 = W[(k0 + 8 + 2 * c) * DD + n];
        const float w11 = W[(k0 + 9 + 2 * c) * DD + n];
        uint32_t h0, l0, h1, l1;
        split2(w00, w01, h0, l0);
        split2(w10, w11, h1, l1);
        g_Wmma[(size_t)(l * NSTEP + s) * 128 + t] = make_uint4(h0, h1, l0, l1);
    } else if (bx < SB_ZERO) {
        const int bi = bx - SB_WSPLIT;
        const int base = bi * 1000;
        for (int i = base + t; i < base + 1000 && i < NN; i += 128) {
            g_cnt[i] = 0;
            g_deg[i] = 0.0f;
        }
        if (bi == 0 && t < SCAN_B) g_flag[t] = 0;
        const int mbase = bi * 32;      // 25 blocks x 32 > NMASK(782)
        for (int i = mbase + t; i < mbase + 32 && i < NMASK; i += 128)
            g_actmask[i] = 0u;
    } else if (bx < SB_INIT) {
        if (t < 128) {
            const int b = t >> 5, d = t & 31;
            ((float*)g_qT)[d * 4 + b] = __ldg(&query_embed[__ldg(&r_index[b]) * DD + d]);
        }
        __syncthreads();
        if (t < DD) {
            const int j = t;
#pragma unroll
            for (int s = 0; s < 3; ++s) {
                float c = 0.0f;
#pragma unroll
                for (int dd = 0; dd < DD; ++dd)
                    c += lin_W[(DD + (4 * dd + 3) * 3 + s) * DD + j];
                g_csum[s * DD + j] = c;
            }
        }
    } else {
        // mlp W1 [64x64] -> fragment-ordered bf16 hi/lo
        const int lane = t & 31, jj = t >> 5;
        const int c = lane & 3, gq = lane >> 2;
#pragma unroll
        for (int jo = 0; jo < 2; ++jo) {
            const int j = jj + 4 * jo;
            const int n = 8 * j + gq;
#pragma unroll
            for (int s = 0; s < 4; ++s) {
                const int k0 = 16 * s;
                const float w00 = mlp_W1[(k0 + 2 * c) * 64 + n];
                const float w01 = mlp_W1[(k0 + 2 * c + 1) * 64 + n];
                const float w10 = mlp_W1[(k0 + 8 + 2 * c) * 64 + n];
                const float w11 = mlp_W1[(k0 + 9 + 2 * c) * 64 + n];
                uint32_t h0, l0, h1, l1;
                split2(w00, w01, h0, l0);
                split2(w10, w11, h1, l1);
                g_W1mma[(s * 8 + j) * 32 + lane] = make_uint4(h0, h1, l0, l1);
            }
        }
    }
}

// ---------------- graph-build kernels ----------------
__global__ void hist_kernel(const int* __restrict__ node_out,
                            const float* __restrict__ ew) {
    const int e = blockIdx.x * 256 + threadIdx.x;
    if (e < NE) {
        const int v = node_out[e];
        atomicAdd(&g_cnt[v], 1);
        atomicAdd(&g_deg[v], ew[e]);
    }
}

// single-kernel decoupled scan
__global__ void __launch_bounds__(1024) scan_kernel() {
    __shared__ int wsum[32];
    __shared__ int woff[32];
    __shared__ float lsum[32];
    __shared__ int sI[SCAN_B];
    __shared__ float sF[SCAN_B];
    const int t = threadIdx.x, wid = t >> 5, lane = t & 31;
    const int b = blockIdx.x;
    const int i = b * 1024 + t;
    const int x = (i < NN) ? g_cnt[i] : 0;
    float y = (i < NN) ? logf(g_deg[i] + 1.0f) : 0.0f;

    int incl = x;
#pragma unroll
    for (int off = 1; off < 32; off <<= 1) {
        int n = __shfl_up_sync(0xffffffffu, incl, off);
        if (lane >= off) incl += n;
    }
#pragma unroll
    for (int off = 16; off > 0; off >>= 1)
        y += __shfl_down_sync(0xffffffffu, y, off);
    if (lane == 31) wsum[wid] = incl;
    if (lane == 0)  lsum[wid] = y;
    __syncthreads();
    if (wid == 0) {
        int s = wsum[lane];
        int si = s;
#pragma unroll
        for (int off = 1; off < 32; off <<= 1) {
            int n = __shfl_up_sync(0xffffffffu, si, off);
            if (lane >= off) si += n;
        }
        woff[lane] = si - s;
        if (lane == 31) g_partI[b] = si;
    }
    __syncthreads();
    if (t == 0) {
        float ftot = 0.0f;
#pragma unroll
        for (int ww = 0; ww < 32; ++ww) ftot += lsum[ww];
        g_partF[b] = ftot;
        __threadfence();
        atomicExch(&g_flag[b], 1);
    }
    if (t < SCAN_B) {
        while (atomicAdd(&g_flag[t], 0) == 0) {}
        sI[t] = g_partI[t];
        sF[t] = g_partF[t];
    }
    __syncthreads();
    int off = 0;
    float gl = 0.0f;
#pragma unroll
    for (int j = 0; j < SCAN_B; ++j) {
        if (j < b) off += sI[j];
        gl += sF[j];
    }
    if (i < NN) {
        const int rp = incl - x + woff[wid] + off;
        g_rowptr[i] = rp;
        g_pos[i] = rp;
        const float mean = gl / (float)NN;
        const float s = logf(g_deg[i] + 1.0f) / mean;
        g_sc[i] = make_float2(s, 1.0f / fmaxf(s, 0.01f));
    }
    if (i == 0) g_rowptr[NN] = NE;
}

// scatter + fused layer-0 head-edge filter (compares are ~free; atomicOr rare)
__global__ void scatter_kernel(const int* __restrict__ node_in,
                               const int* __restrict__ node_out,
                               const int* __restrict__ relation,
                               const float* __restrict__ ew,
                               const int* __restrict__ h_index) {
    const int e = blockIdx.x * 256 + threadIdx.x;
    if (e < NE) {
        const int s = node_in[e];
        const int dv = node_out[e];
        const int p = atomicAdd(&g_pos[dv], 1);
        g_epack[p] = make_int2(s | (relation[e] << 16), __float_as_int(ew[e]));
        const int h0 = __ldg(&h_index[0]), h1 = __ldg(&h_index[1]);
        const int h2 = __ldg(&h_index[2]), h3 = __ldg(&h_index[3]);
        if (s == h0 || s == h1 || s == h2 || s == h3)
            atomicOr(&g_actmask[dv >> 5], 1u << (dv & 31));
    }
}

// ---------------- fused conv layer (R12-proven structure) ----------------
__device__ __forceinline__ uint2 ldcg2u(const uint2* p) {
    uint2 v;
    asm volatile("ld.global.cg.v2.u32 {%0,%1},[%2];"
                 : "=r"(v.x), "=r"(v.y) : "l"(p));
    return v;
}

#define WRITE_PAIR(p, x0, x1)                                              \
    do {                                                                   \
        uint32_t hh_, ll_;                                                 \
        split2((x0).x, (x1).x, hh_, ll_);                                  \
        catH[p][r0] = hh_; catL[p][r0] = ll_;                              \
        split2((x0).y, (x1).y, hh_, ll_);                                  \
        catH[p][r0 + 1] = hh_; catL[p][r0 + 1] = ll_;                      \
        split2((x0).z, (x1).z, hh_, ll_);                                  \
        catH[p][r0 + 2] = hh_; catL[p][r0 + 2] = ll_;                      \
        split2((x0).w, (x1).w, hh_, ll_);                                  \
        catH[p][r0 + 3] = hh_; catL[p][r0 + 3] = ll_;                      \
    } while (0)

#define EDGE_CORE(rv_, hh_, wbits_, mw01o, mw23o)                          \
    do {                                                                   \
        const __half2 wh_ = __float2half2_rn(__int_as_float(wbits_));      \
        const __half2 m01_ = __hmul2(u2h((rv_).x), u2h((hh_).x));          \
        const __half2 m23_ = __hmul2(u2h((rv_).y), u2h((hh_).y));          \
        mw01o = __hmul2(m01_, wh_);                                        \
        mw23o = __hmul2(m23_, wh_);                                        \
        mxh01 = __hmax2(mxh01, mw01o); mxh23 = __hmax2(mxh23, mw23o);      \
        mnh01 = __hmin2(mnh01, mw01o); mnh23 = __hmin2(mnh23, mw23o);      \
        sqh01 = __hfma2(m01_, mw01o, sqh01);                               \
        sqh23 = __hfma2(m23_, mw23o, sqh23);                               \
    } while (0)

__global__ void __launch_bounds__(128) conv_kernel(
    const float* __restrict__ lin_b,
    const uint2* __restrict__ h16_in, uint2* __restrict__ h16_out,
    const int* __restrict__ h_index, int layer)
{
    __shared__ uint32_t catH[KD / 2][17];
    __shared__ uint32_t catL[KD / 2][17];
    __shared__ int s_act[4];
    __shared__ float2 s_scl[4];
    float* sD = (float*)catL;

    const int t = threadIdx.x, w = t >> 5, lane = t & 31;
    const int v = blockIdx.x * 4 + w;
    const int d = lane;
    const uint2* relin = g_relinH + (size_t)layer * RR * DD + d;

    // ---- message phase (warp per node) ----
    {
        const int4 h = *(const int4*)h_index;
        const float4 q = g_qT[d];
        const float4 m0 = make_float4(v == h.x ? q.x : 0.f,
                                      v == h.y ? q.y : 0.f,
                                      v == h.z ? q.z : 0.f,
                                      v == h.w ? q.w : 0.f);
        int p = g_rowptr[v];
        const int e_ = g_rowptr[v + 1];
        const int degv = e_ - p;
        int act;
        float4 hv;
        float4 sumF = make_float4(0.f, 0.f, 0.f, 0.f);
        float4 sqF = sumF, mxF = sumF, mnF = sumF;

        if (layer == 0) {
            hv = m0;   // layer-0 hidden IS the boundary
            const int ishead = (v == h.x) | (v == h.y) | (v == h.z) | (v == h.w);
            const int masked = (g_actmask[v >> 5] >> (v & 31)) & 1;
            act = ishead;
            if (ishead | masked) {
                float4 sum = m0, mx = m0, mn = m0;
                float4 sq = make_float4(m0.x * m0.x, m0.y * m0.y, m0.z * m0.z, m0.w * m0.w);
                int nacc = 0;
                for (; p < e_; ++p) {
                    const int2 ep = __ldg(&g_epack[p]);
                    const int nin = ep.x & 0xFFFF;
                    if (nin == h.x || nin == h.y || nin == h.z || nin == h.w) {
                        act = 1; ++nacc;
                        const uint2 rvh = __ldg(&relin[(ep.x >> 16) * DD]);
                        const float2 r01 = __half22float2(u2h(rvh.x));
                        const float2 r23 = __half22float2(u2h(rvh.y));
                        const float4 hh = make_float4(nin == h.x ? q.x : 0.f,
                                                      nin == h.y ? q.y : 0.f,
                                                      nin == h.z ? q.z : 0.f,
                                                      nin == h.w ? q.w : 0.f);
                        const float wgt = __int_as_float(ep.y);
                        float m, mw;
                        m = r01.x * hh.x; mw = m * wgt; sum.x += mw; sq.x = fmaf(m, mw, sq.x); mx.x = fmaxf(mx.x, mw); mn.x = fminf(mn.x, mw);
                        m = r01.y * hh.y; mw = m * wgt; sum.y += mw; sq.y = fmaf(m, mw, sq.y); mx.y = fmaxf(mx.y, mw); mn.y = fminf(mn.y, mw);
                        m = r23.x * hh.z; mw = m * wgt; sum.z += mw; sq.z = fmaf(m, mw, sq.z); mx.z = fmaxf(mx.z, mw); mn.z = fminf(mn.z, mw);
                        m = r23.y * hh.w; mw = m * wgt; sum.w += mw; sq.w = fmaf(m, mw, sq.w); mx.w = fmaxf(mx.w, mw); mn.w = fminf(mn.w, mw);
                    }
                }
                if (nacc < degv) {
                    mx.x = fmaxf(mx.x, 0.f); mx.y = fmaxf(mx.y, 0.f); mx.z = fmaxf(mx.z, 0.f); mx.w = fmaxf(mx.w, 0.f);
                    mn.x = fminf(mn.x, 0.f); mn.y = fminf(mn.y, 0.f); mn.z = fminf(mn.z, 0.f); mn.w = fminf(mn.w, 0.f);
                }
                sumF = sum; sqF = sq; mxF = mx; mnF = mn;
            }
        } else {
            act = 1;
            hv = cvt_rv(__ldg(&h16_in[v * DD + d]));
            ull sum01 = pk2(m0.x, m0.y), sum23 = pk2(m0.z, m0.w);
            __half2 sqh01 = __floats2half2_rn(m0.x * m0.x, m0.y * m0.y);
            __half2 sqh23 = __floats2half2_rn(m0.z * m0.z, m0.w * m0.w);
            __half2 mxh01 = __floats2half2_rn(m0.x, m0.y);
            __half2 mxh23 = __floats2half2_rn(m0.z, m0.w);
            __half2 mnh01 = mxh01, mnh23 = mxh23;

            const int nfull = (e_ - p) >> 2;
            if (nfull > 0) {
                int2 ee[4];
#pragma unroll
                for (int j = 0; j < 4; ++j) ee[j] = __ldg(&g_epack[p + j]);
                for (int b = 0; b < nfull; ++b) {
                    uint2 rv[4], hh[4];
#pragma unroll
                    for (int j = 0; j < 4; ++j) {
                        rv[j] = __ldg(&relin[(ee[j].x >> 16) * DD]);
                        hh[j] = ldcg2u(&h16_in[(ee[j].x & 0xFFFF) * DD + d]);
                    }
                    const int wb0 = ee[0].y, wb1 = ee[1].y;
                    const int wb2 = ee[2].y, wb3 = ee[3].y;
                    if (b + 1 < nfull) {
                        const int pn = p + 4 * (b + 1);
#pragma unroll
                        for (int j = 0; j < 4; ++j) ee[j] = __ldg(&g_epack[pn + j]);
                    }
                    __half2 a01, a23, b01, b23, c01, c23, d01, d23;
                    EDGE_CORE(rv[0], hh[0], wb0, a01, a23);
                    EDGE_CORE(rv[1], hh[1], wb1, b01, b23);
                    EDGE_CORE(rv[2], hh[2], wb2, c01, c23);
                    EDGE_CORE(rv[3], hh[3], wb3, d01, d23);
                    const __half2 t01 = __hadd2(__hadd2(a01, b01), __hadd2(c01, d01));
                    const __half2 t23 = __hadd2(__hadd2(a23, b23), __hadd2(c23, d23));
                    sum01 = add2(sum01, h2f2(t01));
                    sum23 = add2(sum23, h2f2(t23));
                }
                p += nfull * 4;
            }
            for (; p < e_; ++p) {
                const int2 e0 = __ldg(&g_epack[p]);
                const uint2 rv0 = __ldg(&relin[(e0.x >> 16) * DD]);
                const uint2 hh0 = ldcg2u(&h16_in[(e0.x & 0xFFFF) * DD + d]);
                __half2 a01, a23;
                EDGE_CORE(rv0, hh0, e0.y, a01, a23);
                sum01 = add2(sum01, h2f2(a01));
                sum23 = add2(sum23, h2f2(a23));
            }
            const float2 s01 = unpk(sum01), s23 = unpk(sum23);
            const float2 q01 = __half22float2(sqh01), q23 = __half22float2(sqh23);
            const float2 x01 = __half22float2(mxh01), x23 = __half22float2(mxh23);
            const float2 n01 = __half22float2(mnh01), n23 = __half22float2(mnh23);
            sumF = make_float4(s01.x, s01.y, s23.x, s23.y);
            sqF  = make_float4(q01.x, q01.y, q23.x, q23.y);
            mxF  = make_float4(x01.x, x01.y, x23.x, x23.y);
            mnF  = make_float4(n01.x, n01.y, n23.x, n23.y);
        }

        if (lane == 0) { s_act[w] = act; s_scl[w] = g_sc[v]; }

        if (act) {
            const float inv = 1.0f / (float)(degv + 1);
            float4 mean, var, sd2;
            mean.x = sumF.x * inv; mean.y = sumF.y * inv; mean.z = sumF.z * inv; mean.w = sumF.w * inv;
            var.x = sqF.x * inv - mean.x * mean.x; var.y = sqF.y * inv - mean.y * mean.y;
            var.z = sqF.z * inv - mean.z * mean.z; var.w = sqF.w * inv - mean.w * mean.w;
            sd2.x = sqrtf(fmaxf(var.x, EPSF)); sd2.y = sqrtf(fmaxf(var.y, EPSF));
            sd2.z = sqrtf(fmaxf(var.z, EPSF)); sd2.w = sqrtf(fmaxf(var.w, EPSF));
            const float2 sc = g_sc[v];
            const int r0 = w * 4;

            float4 hv1;
            hv1.x = __shfl_down_sync(0xffffffffu, hv.x, 1);
            hv1.y = __shfl_down_sync(0xffffffffu, hv.y, 1);
            hv1.z = __shfl_down_sync(0xffffffffu, hv.z, 1);
            hv1.w = __shfl_down_sync(0xffffffffu, hv.w, 1);
            if ((d & 1) == 0) WRITE_PAIR(d >> 1, hv, hv1);

            float4 f[12];
            const float4 st4[4] = {mean, mxF, mnF, sd2};
#pragma unroll
            for (int si = 0; si < 4; ++si) {
                const float4 fv = st4[si];
                f[si * 3 + 0] = fv;
                f[si * 3 + 1] = make_float4(fv.x * sc.x, fv.y * sc.x, fv.z * sc.x, fv.w * sc.x);
                f[si * 3 + 2] = make_float4(fv.x * sc.y, fv.y * sc.y, fv.z * sc.y, fv.w * sc.y);
            }
            const int pb = 16 + 6 * d;
#pragma unroll
            for (int pi = 0; pi < 6; ++pi)
                WRITE_PAIR(pb + pi, f[2 * pi], f[2 * pi + 1]);
        }
    }
    __syncthreads();

    const int anyact = s_act[0] | s_act[1] | s_act[2] | s_act[3];

    // ---- GEMM via mma.sync bf16 3-split ----
    float d0 = 0.f, d1 = 0.f, d2 = 0.f, d3 = 0.f;
    const int c = lane & 3, g = lane >> 2;
    if (anyact) {
        const uint4* Wp = g_Wmma + (size_t)layer * NSTEP * 128 + (w * 32 + lane);
#pragma unroll
        for (int s = 0; s < NSTEP; ++s) {
            const uint4 wv = __ldg(&Wp[(size_t)s * 128]);
            const int pA = s * 8 + c, pB = s * 8 + 4 + c;
            const uint32_t ah0 = catH[pA][g], ah1 = catH[pA][g + 8];
            const uint32_t ah2 = catH[pB][g], ah3 = catH[pB][g + 8];
            const uint32_t al0 = catL[pA][g], al1 = catL[pA][g + 8];
            const uint32_t al2 = catL[pB][g], al3 = catL[pB][g + 8];
            mma16816(d0, d1, d2, d3, ah0, ah1, ah2, ah3, wv.x, wv.y);
            mma16816(d0, d1, d2, d3, ah0, ah1, ah2, ah3, wv.z, wv.w);
            mma16816(d0, d1, d2, d3, al0, al1, al2, al3, wv.x, wv.y);
        }
    }
    __syncthreads();
    if (anyact) {
        const int j0 = 8 * w + 2 * c;
        sD[g * 33 + j0] = d0;       sD[g * 33 + j0 + 1] = d1;
        sD[(g + 8) * 33 + j0] = d2; sD[(g + 8) * 33 + j0 + 1] = d3;
    }
    __syncthreads();

    // ---- epilogue: fp16 hidden only ----
    {
        const float bias = lin_b[layer * DD + lane];
        float4 o;
        if (s_act[w]) {
            o = make_float4(fmaxf(sD[(w * 4 + 0) * 33 + lane] + bias, 0.0f),
                            fmaxf(sD[(w * 4 + 1) * 33 + lane] + bias, 0.0f),
                            fmaxf(sD[(w * 4 + 2) * 33 + lane] + bias, 0.0f),
                            fmaxf(sD[(w * 4 + 3) * 33 + lane] + bias, 0.0f));
        } else {
            const float sd = sqrtf(EPSF);
            const float2 sc = s_scl[w];
            const float c2 = g_csum[lane] + sc.x * g_csum[DD + lane] + sc.y * g_csum[2 * DD + lane];
            const float val = fmaxf(bias + sd * c2, 0.0f);
            o = make_float4(val, val, val, val);
        }
        const __half2 o01 = __floats2half2_rn(o.x, o.y);
        const __half2 o23 = __floats2half2_rn(o.z, o.w);
        uint2 ho;
        ho.x = h2u(o01);
        ho.y = h2u(o23);
        h16_out[v * DD + lane] = ho;
    }
}

// ---------------- final MLP scoring via mma (block = 32 nodes / iter) ----------------
__global__ void __launch_bounds__(256) mlp_kernel(
    const uint2* __restrict__ hid16,
    const float* __restrict__ b1,
    const float* __restrict__ W2, const float* __restrict__ b2,
    float* __restrict__ out)
{
    __shared__ uint32_t fAH[32][132];
    __shared__ uint32_t fAL[32][132];
    __shared__ float b1s[64];
    __shared__ float W2s[64];

    const int t = threadIdx.x, w = t >> 5, lane = t & 31;
    const int c = lane & 3, g = lane >> 2;
    if (t < 64) { b1s[t] = b1[t]; W2s[t] = W2[t]; }

    for (int it = 0; it < MLP_IT2; ++it) {
        const int vbase = (blockIdx.x * MLP_IT2 + it) * 32;
        __syncthreads();
        {
            const int r = t >> 1, half = t & 1;
            const int v = vbase + (r >> 2), b = r & 3;
            if (half == 0) {
                const uint2* hp = hid16 + (size_t)v * DD;
#pragma unroll
                for (int kp = 0; kp < 16; ++kp) {
                    float x0 = 0.f, x1 = 0.f;
                    if (v < NN) {
                        x0 = h16get(__ldg(&hp[2 * kp]), b);
                        x1 = h16get(__ldg(&hp[2 * kp + 1]), b);
                    }
                    uint32_t hh, ll;
                    split2(x0, x1, hh, ll);
                    fAH[kp][r] = hh; fAL[kp][r] = ll;
                }
            } else {
#pragma unroll
                for (int kp = 0; kp < 16; ++kp) {
                    const float4 q0 = g_qT[2 * kp];
                    const float4 q1 = g_qT[2 * kp + 1];
                    const float x0 = (b == 0) ? q0.x : (b == 1) ? q0.y : (b == 2) ? q0.z : q0.w;
                    const float x1 = (b == 0) ? q1.x : (b == 1) ? q1.y : (b == 2) ? q1.z : q1.w;
                    uint32_t hh, ll;
                    split2(x0, x1, hh, ll);
                    fAH[16 + kp][r] = hh; fAL[16 + kp][r] = ll;
                }
            }
        }
        __syncthreads();

        const int base = w * 16;
        float sLo = 0.f, sHi = 0.f;
#pragma unroll
        for (int j = 0; j < 8; ++j) {
            float d0 = 0.f, d1 = 0.f, d2 = 0.f, d3 = 0.f;
#pragma unroll
            for (int s = 0; s < 4; ++s) {
                const uint4 wv = __ldg(&g_W1mma[(s * 8 + j) * 32 + lane]);
                const int pA = s * 8 + c, pB = pA + 4;
                const uint32_t ah0 = fAH[pA][base + g], ah1 = fAH[pA][base + g + 8];
                const uint32_t ah2 = fAH[pB][base + g], ah3 = fAH[pB][base + g + 8];
                const uint32_t al0 = fAL[pA][base + g], al1 = fAL[pA][base + g + 8];
                const uint32_t al2 = fAL[pB][base + g], al3 = fAL[pB][base + g + 8];
                mma16816(d0, d1, d2, d3, ah0, ah1, ah2, ah3, wv.x, wv.y);
                mma16816(d0, d1, d2, d3, ah0, ah1, ah2, ah3, wv.z, wv.w);
                mma16816(d0, d1, d2, d3, al0, al1, al2, al3, wv.x, wv.y);
            }
            const int n0 = 8 * j + 2 * c, n1 = n0 + 1;
            sLo += fmaxf(d0 + b1s[n0], 0.0f) * W2s[n0] + fmaxf(d1 + b1s[n1], 0.0f) * W2s[n1];
            sHi += fmaxf(d2 + b1s[n0], 0.0f) * W2s[n0] + fmaxf(d3 + b1s[n1], 0.0f) * W2s[n1];
        }
        sLo += __shfl_xor_sync(0xffffffffu, sLo, 1);
        sLo += __shfl_xor_sync(0xffffffffu, sLo, 2);
        sHi += __shfl_xor_sync(0xffffffffu, sHi, 1);
        sHi += __shfl_xor_sync(0xffffffffu, sHi, 2);
        if (c == 0) {
            const float bias2 = __ldg(&b2[0]);
            const int R0 = base + g;
            const int v0 = vbase + (R0 >> 2), b0 = R0 & 3;
            if (v0 < NN) out[b0 * NN + v0] = sLo + bias2;
            const int R1 = base + g + 8;
            const int v1 = vbase + (R1 >> 2), bb1 = R1 & 3;
            if (v1 < NN) out[bb1 * NN + v1] = sHi + bias2;
        }
    }
}

// ---------------- launch ----------------
extern "C" void kernel_launch(void* const* d_in, const int* in_sizes, int n_in,
                              void* d_out, int out_size) {
    const int*   node_in     = (const int*)  d_in[0];
    const int*   node_out    = (const int*)  d_in[1];
    const int*   relation    = (const int*)  d_in[2];
    const float* edge_weight = (const float*)d_in[3];
    const int*   h_index     = (const int*)  d_in[4];
    const int*   r_index     = (const int*)  d_in[5];
    const float* query_embed = (const float*)d_in[6];
    const float* rel_W  = (const float*)d_in[7];
    const float* rel_b  = (const float*)d_in[8];
    const float* lin_W  = (const float*)d_in[9];
    const float* lin_b  = (const float*)d_in[10];
    const float* mlp_W1 = (const float*)d_in[11];
    const float* mlp_b1 = (const float*)d_in[12];
    const float* mlp_W2 = (const float*)d_in[13];
    const float* mlp_b2 = (const float*)d_in[14];
    float* out = (float*)d_out;

    uint2 *h16A, *h16B;
    cudaGetSymbolAddress((void**)&h16A, g_h16A);
    cudaGetSymbolAddress((void**)&h16B, g_h16B);

    setup_kernel<<<SB_TOTAL, 128>>>(h_index, r_index, query_embed,
                                    lin_W, rel_W, rel_b, mlp_W1);  // 0
    hist_kernel<<<(NE + 255) / 256, 256>>>(node_out, edge_weight); // 1
    scan_kernel<<<SCAN_B, 1024>>>();                               // 2
    scatter_kernel<<<(NE + 255) / 256, 256>>>(node_in, node_out, relation,
                                              edge_weight, h_index); // 3

    const uint2* h16in = h16A;       // unused at layer 0
    uint2* h16outs[4] = {h16A, h16B, h16A, h16B};
    for (int l = 0; l < NL; ++l) {
        conv_kernel<<<NN / 4, 128>>>(lin_b, h16in, h16outs[l], h_index, l); // 4..7
        h16in = h16outs[l];
    }
    mlp_kernel<<<(NN + 32 * MLP_IT2 - 1) / (32 * MLP_IT2), 256>>>(
        h16in, mlp_b1, mlp_W2, mlp_b2, out);                       // 8
}

// round 17
// speedup vs baseline: 1.5804x; 1.2988x over previous
#include <cuda_runtime.h>
#include <cuda_fp16.h>
#include <math.h>
#include <stdint.h>

#define NN 25000
#define NE 500000
#define BQ 4
#define DD 32
#define RR 474
#define NL 4
#define KD 416          // 13*D
#define NSTEP 26        // KD/16 k-steps
#define EPSF 1e-6f
#define SCAN_B 25       // ceil(25000/1024)
#define MLP_IT2 2       // 32-node tiles per mlp block
#define NMASK ((NN + 31) / 32)

// setup_kernel block partition
#define SB_RELIN (NL * RR)                 // 1896
#define SB_WSPLIT (SB_RELIN + NL * NSTEP)  // +104
#define SB_ZERO (SB_WSPLIT + 25)           // +25 (zero cnt/deg/flags/mask)
#define SB_INIT (SB_ZERO + 1)              // +1 (init)
#define SB_TOTAL (SB_INIT + 1)             // +1 (W1 fragment split)

typedef unsigned long long ull;

// ---- packed fp32x2 helpers ----
__device__ __forceinline__ ull fma2(ull a, ull b, ull c) {
    ull d; asm("fma.rn.f32x2 %0,%1,%2,%3;" : "=l"(d) : "l"(a), "l"(b), "l"(c)); return d;
}
__device__ __forceinline__ ull add2(ull a, ull b) {
    ull d; asm("add.rn.f32x2 %0,%1,%2;" : "=l"(d) : "l"(a), "l"(b)); return d;
}
__device__ __forceinline__ ull pk2(float x, float y) {
    ull r; asm("mov.b64 %0,{%1,%2};" : "=l"(r) : "f"(x), "f"(y)); return r;
}
__device__ __forceinline__ float2 unpk(ull a) {
    float2 f; asm("mov.b64 {%0,%1},%2;" : "=f"(f.x), "=f"(f.y) : "l"(a)); return f;
}
__device__ __forceinline__ ull h2f2(__half2 h) {
    const float2 f = __half22float2(h);
    return pk2(f.x, f.y);
}
__device__ __forceinline__ __half2 u2h(uint32_t u) { return *(const __half2*)&u; }
__device__ __forceinline__ uint32_t h2u(__half2 h) { return *(const uint32_t*)&h; }
__device__ __forceinline__ float4 cvt_rv(const uint2 rh) {
    const float2 f01 = __half22float2(u2h(rh.x));
    const float2 f23 = __half22float2(u2h(rh.y));
    return make_float4(f01.x, f01.y, f23.x, f23.y);
}
// extract b-th fp16 component of a (b0,b1,b2,b3) uint2 as float
__device__ __forceinline__ float h16get(const uint2 e, int b) {
    const uint32_t u = (b < 2) ? e.x : e.y;
    const float2 f = __half22float2(u2h(u));
    return (b & 1) ? f.y : f.x;
}
// pack (x0,x1) to a single fp16x2 word
__device__ __forceinline__ uint32_t pkh2(float x0, float x1) {
    return h2u(__floats2half2_rn(x0, x1));
}
// split (x0,x1) into fp16 hi pair + fp16 lo pair (2-term ~22-bit)
__device__ __forceinline__ void split2h(float x0, float x1, uint32_t& h, uint32_t& l) {
    const __half2 hp = __floats2half2_rn(x0, x1);
    const float2 hf = __half22float2(hp);
    const __half2 lp = __floats2half2_rn(x0 - hf.x, x1 - hf.y);
    h = h2u(hp); l = h2u(lp);
}

__device__ __forceinline__ void mma16816h(float& d0, float& d1, float& d2, float& d3,
                                          uint32_t a0, uint32_t a1, uint32_t a2, uint32_t a3,
                                          uint32_t b0, uint32_t b1) {
    asm volatile("mma.sync.aligned.m16n8k16.row.col.f32.f16.f16.f32 "
                 "{%0,%1,%2,%3},{%4,%5,%6,%7},{%8,%9},{%0,%1,%2,%3};"
                 : "+f"(d0), "+f"(d1), "+f"(d2), "+f"(d3)
                 : "r"(a0), "r"(a1), "r"(a2), "r"(a3), "r"(b0), "r"(b1));
}

// ---------------- scratch ----------------
__device__ int    g_cnt[NN];
__device__ float  g_deg[NN];
__device__ int    g_rowptr[NN + 1];
__device__ int    g_pos[NN];
__device__ int2   g_epack[NE];          // CSR-ordered (nin | rel<<16, w_bits)
__device__ float2 g_sc[NN];             // (s1, s2)
__device__ int    g_flag[SCAN_B];
__device__ int    g_partI[SCAN_B];
__device__ float  g_partF[SCAN_B];
__device__ unsigned g_actmask[NMASK];   // layer-0: dst nodes of head-source edges
__device__ uint2  g_h16A[NN * DD];      // fp16x2 hidden state
__device__ uint2  g_h16B[NN * DD];
__device__ uint2  g_relinH[NL * RR * DD]; // fp16x2 pairs: (b0,b1),(b2,b3)
__device__ float4 g_qT[DD];             // [d] -> b-vector
__device__ float  g_csum[3 * DD];       // layer-0 std-column sums per scale
__device__ uint4  g_Wmma[NL * NSTEP * 128]; // fragment-ordered fp16 hi/lo conv weights
__device__ uint4  g_W1mma[32 * 32];     // fragment-ordered fp16 hi/lo mlp W1

// ---------------- fused setup (input-only work, launch #0) ----------------
__global__ void __launch_bounds__(128) setup_kernel(
    const int* __restrict__ h_index,
    const int* __restrict__ r_index,
    const float* __restrict__ query_embed,
    const float* __restrict__ lin_W,
    const float* __restrict__ rel_W,
    const float* __restrict__ rel_b,
    const float* __restrict__ mlp_W1)
{
    const int bx = blockIdx.x;
    const int t = threadIdx.x;

    if (bx < SB_RELIN) {
        __shared__ float acc_s[BQ][DD];
        const int l = bx / RR, r = bx - l * RR;
        const int d = t & 31, b = t >> 5;
        const int ri = __ldg(&r_index[b]);
        const float* W = rel_W + (size_t)l * DD * RR * DD + (size_t)r * DD + d;
        float acc = rel_b[(size_t)l * RR * DD + r * DD + d];
#pragma unroll
        for (int k = 0; k < DD; ++k)
            acc += __ldg(&query_embed[ri * DD + k]) * W[(size_t)k * RR * DD];
        acc_s[b][d] = acc;
        __syncthreads();
        if (t < DD) {
            uint2 o;
            o.x = pkh2(acc_s[0][t], acc_s[1][t]);
            o.y = pkh2(acc_s[2][t], acc_s[3][t]);
            g_relinH[(size_t)(l * RR + r) * DD + t] = o;
        }
    } else if (bx < SB_WSPLIT) {
        const int i = bx - SB_RELIN;
        const int l = i / NSTEP, s = i % NSTEP;
        const int w = t >> 5, lane = t & 31;
        const int c = lane & 3, n = 8 * w + (lane >> 2);
        const int k0 = 16 * s;
        const float* W = lin_W + (size_t)l * KD * DD;
        const float w00 = W[(k0 + 2 * c) * DD + n];
        const float w01 = W[(k0 + 2 * c + 1) * DD + n];
        const float w10 = W[(k0 + 8 + 2 * c) * DD + n];
        const float w11 = W[(k0 + 9 + 2 * c) * DD + n];
        uint32_t h0, l0, h1, l1;
        split2h(w00, w01, h0, l0);
        split2h(w10, w11, h1, l1);
        g_Wmma[(size_t)(l * NSTEP + s) * 128 + t] = make_uint4(h0, h1, l0, l1);
    } else if (bx < SB_ZERO) {
        const int bi = bx - SB_WSPLIT;
        const int base = bi * 1000;
        for (int i = base + t; i < base + 1000 && i < NN; i += 128) {
            g_cnt[i] = 0;
            g_deg[i] = 0.0f;
        }
        if (bi == 0 && t < SCAN_B) g_flag[t] = 0;
        const int mbase = bi * 32;
        for (int i = mbase + t; i < mbase + 32 && i < NMASK; i += 128)
            g_actmask[i] = 0u;
    } else if (bx < SB_INIT) {
        if (t < 128) {
            const int b = t >> 5, d = t & 31;
            ((float*)g_qT)[d * 4 + b] = __ldg(&query_embed[__ldg(&r_index[b]) * DD + d]);
        }
        __syncthreads();
        if (t < DD) {
            const int j = t;
#pragma unroll
            for (int s = 0; s < 3; ++s) {
                float c = 0.0f;
#pragma unroll
                for (int dd = 0; dd < DD; ++dd)
                    c += lin_W[(DD + (4 * dd + 3) * 3 + s) * DD + j];
                g_csum[s * DD + j] = c;
            }
        }
    } else {
        // mlp W1 [64x64] -> fragment-ordered fp16 hi/lo
        const int lane = t & 31, jj = t >> 5;
        const int c = lane & 3, gq = lane >> 2;
#pragma unroll
        for (int jo = 0; jo < 2; ++jo) {
            const int j = jj + 4 * jo;
            const int n = 8 * j + gq;
#pragma unroll
            for (int s = 0; s < 4; ++s) {
                const int k0 = 16 * s;
                const float w00 = mlp_W1[(k0 + 2 * c) * 64 + n];
                const float w01 = mlp_W1[(k0 + 2 * c + 1) * 64 + n];
                const float w10 = mlp_W1[(k0 + 8 + 2 * c) * 64 + n];
                const float w11 = mlp_W1[(k0 + 9 + 2 * c) * 64 + n];
                uint32_t h0, l0, h1, l1;
                split2h(w00, w01, h0, l0);
                split2h(w10, w11, h1, l1);
                g_W1mma[(s * 8 + j) * 32 + lane] = make_uint4(h0, h1, l0, l1);
            }
        }
    }
}

// ---------------- graph-build kernels ----------------
__global__ void hist_kernel(const int* __restrict__ node_out,
                            const float* __restrict__ ew) {
    const int e = blockIdx.x * 256 + threadIdx.x;
    if (e < NE) {
        const int v = node_out[e];
        atomicAdd(&g_cnt[v], 1);
        atomicAdd(&g_deg[v], ew[e]);
    }
}

// single-kernel decoupled scan
__global__ void __launch_bounds__(1024) scan_kernel() {
    __shared__ int wsum[32];
    __shared__ int woff[32];
    __shared__ float lsum[32];
    __shared__ int sI[SCAN_B];
    __shared__ float sF[SCAN_B];
    const int t = threadIdx.x, wid = t >> 5, lane = t & 31;
    const int b = blockIdx.x;
    const int i = b * 1024 + t;
    const int x = (i < NN) ? g_cnt[i] : 0;
    float y = (i < NN) ? logf(g_deg[i] + 1.0f) : 0.0f;

    int incl = x;
#pragma unroll
    for (int off = 1; off < 32; off <<= 1) {
        int n = __shfl_up_sync(0xffffffffu, incl, off);
        if (lane >= off) incl += n;
    }
#pragma unroll
    for (int off = 16; off > 0; off >>= 1)
        y += __shfl_down_sync(0xffffffffu, y, off);
    if (lane == 31) wsum[wid] = incl;
    if (lane == 0)  lsum[wid] = y;
    __syncthreads();
    if (wid == 0) {
        int s = wsum[lane];
        int si = s;
#pragma unroll
        for (int off = 1; off < 32; off <<= 1) {
            int n = __shfl_up_sync(0xffffffffu, si, off);
            if (lane >= off) si += n;
        }
        woff[lane] = si - s;
        if (lane == 31) g_partI[b] = si;
    }
    __syncthreads();
    if (t == 0) {
        float ftot = 0.0f;
#pragma unroll
        for (int ww = 0; ww < 32; ++ww) ftot += lsum[ww];
        g_partF[b] = ftot;
        __threadfence();
        atomicExch(&g_flag[b], 1);
    }
    if (t < SCAN_B) {
        while (atomicAdd(&g_flag[t], 0) == 0) {}
        sI[t] = g_partI[t];
        sF[t] = g_partF[t];
    }
    __syncthreads();
    int off = 0;
    float gl = 0.0f;
#pragma unroll
    for (int j = 0; j < SCAN_B; ++j) {
        if (j < b) off += sI[j];
        gl += sF[j];
    }
    if (i < NN) {
        const int rp = incl - x + woff[wid] + off;
        g_rowptr[i] = rp;
        g_pos[i] = rp;
        const float mean = gl / (float)NN;
        const float s = logf(g_deg[i] + 1.0f) / mean;
        g_sc[i] = make_float2(s, 1.0f / fmaxf(s, 0.01f));
    }
    if (i == 0) g_rowptr[NN] = NE;
}

// scatter + fused layer-0 head-edge filter
__global__ void scatter_kernel(const int* __restrict__ node_in,
                               const int* __restrict__ node_out,
                               const int* __restrict__ relation,
                               const float* __restrict__ ew,
                               const int* __restrict__ h_index) {
    const int e = blockIdx.x * 256 + threadIdx.x;
    if (e < NE) {
        const int s = node_in[e];
        const int dv = node_out[e];
        const int p = atomicAdd(&g_pos[dv], 1);
        g_epack[p] = make_int2(s | (relation[e] << 16), __float_as_int(ew[e]));
        const int h0 = __ldg(&h_index[0]), h1 = __ldg(&h_index[1]);
        const int h2 = __ldg(&h_index[2]), h3 = __ldg(&h_index[3]);
        if (s == h0 || s == h1 || s == h2 || s == h3)
            atomicOr(&g_actmask[dv >> 5], 1u << (dv & 31));
    }
}

// ---------------- fused conv layer ----------------
__device__ __forceinline__ uint2 ldcg2u(const uint2* p) {
    uint2 v;
    asm volatile("ld.global.cg.v2.u32 {%0,%1},[%2];"
                 : "=r"(v.x), "=r"(v.y) : "l"(p));
    return v;
}

// fp16 cat: one word per k-pair per row
#define WRITE_PAIRF(p, x0, x1)                                             \
    do {                                                                   \
        catF[p][r0]     = pkh2((x0).x, (x1).x);                            \
        catF[p][r0 + 1] = pkh2((x0).y, (x1).y);                            \
        catF[p][r0 + 2] = pkh2((x0).z, (x1).z);                            \
        catF[p][r0 + 3] = pkh2((x0).w, (x1).w);                            \
    } while (0)

#define EDGE_CORE(rv_, hh_, wbits_, mw01o, mw23o)                          \
    do {                                                                   \
        const __half2 wh_ = __float2half2_rn(__int_as_float(wbits_));      \
        const __half2 m01_ = __hmul2(u2h((rv_).x), u2h((hh_).x));          \
        const __half2 m23_ = __hmul2(u2h((rv_).y), u2h((hh_).y));          \
        mw01o = __hmul2(m01_, wh_);                                        \
        mw23o = __hmul2(m23_, wh_);                                        \
        mxh01 = __hmax2(mxh01, mw01o); mxh23 = __hmax2(mxh23, mw23o);      \
        mnh01 = __hmin2(mnh01, mw01o); mnh23 = __hmin2(mnh23, mw23o);      \
        sqh01 = __hfma2(m01_, mw01o, sqh01);                               \
        sqh23 = __hfma2(m23_, mw23o, sqh23);                               \
    } while (0)

__global__ void __launch_bounds__(128) conv_kernel(
    const float* __restrict__ lin_b,
    const uint2* __restrict__ h16_in, uint2* __restrict__ h16_out,
    const int* __restrict__ h_index, int layer)
{
    __shared__ uint32_t catF[KD / 2][17];   // 14.1KB (fp16x2; sD aliases post-GEMM)
    __shared__ int s_act[4];
    __shared__ float2 s_scl[4];
    float* sD = (float*)catF;               // 16x33 floats = 8.25KB, fits

    const int t = threadIdx.x, w = t >> 5, lane = t & 31;
    const int v = blockIdx.x * 4 + w;
    const int d = lane;
    const uint2* relin = g_relinH + (size_t)layer * RR * DD + d;

    // ---- message phase (warp per node) ----
    {
        const int4 h = *(const int4*)h_index;
        const float4 q = g_qT[d];
        const float4 m0 = make_float4(v == h.x ? q.x : 0.f,
                                      v == h.y ? q.y : 0.f,
                                      v == h.z ? q.z : 0.f,
                                      v == h.w ? q.w : 0.f);
        int p = g_rowptr[v];
        const int e_ = g_rowptr[v + 1];
        const int degv = e_ - p;
        int act;
        float4 hv;
        float4 sumF = make_float4(0.f, 0.f, 0.f, 0.f);
        float4 sqF = sumF, mxF = sumF, mnF = sumF;

        if (layer == 0) {
            hv = m0;
            const int ishead = (v == h.x) | (v == h.y) | (v == h.z) | (v == h.w);
            const int masked = (g_actmask[v >> 5] >> (v & 31)) & 1;
            act = ishead;
            if (ishead | masked) {
                float4 sum = m0, mx = m0, mn = m0;
                float4 sq = make_float4(m0.x * m0.x, m0.y * m0.y, m0.z * m0.z, m0.w * m0.w);
                int nacc = 0;
                for (; p < e_; ++p) {
                    const int2 ep = __ldg(&g_epack[p]);
                    const int nin = ep.x & 0xFFFF;
                    if (nin == h.x || nin == h.y || nin == h.z || nin == h.w) {
                        act = 1; ++nacc;
                        const uint2 rvh = __ldg(&relin[(ep.x >> 16) * DD]);
                        const float2 r01 = __half22float2(u2h(rvh.x));
                        const float2 r23 = __half22float2(u2h(rvh.y));
                        const float4 hh = make_float4(nin == h.x ? q.x : 0.f,
                                                      nin == h.y ? q.y : 0.f,
                                                      nin == h.z ? q.z : 0.f,
                                                      nin == h.w ? q.w : 0.f);
                        const float wgt = __int_as_float(ep.y);
                        float m, mw;
                        m = r01.x * hh.x; mw = m * wgt; sum.x += mw; sq.x = fmaf(m, mw, sq.x); mx.x = fmaxf(mx.x, mw); mn.x = fminf(mn.x, mw);
                        m = r01.y * hh.y; mw = m * wgt; sum.y += mw; sq.y = fmaf(m, mw, sq.y); mx.y = fmaxf(mx.y, mw); mn.y = fminf(mn.y, mw);
                        m = r23.x * hh.z; mw = m * wgt; sum.z += mw; sq.z = fmaf(m, mw, sq.z); mx.z = fmaxf(mx.z, mw); mn.z = fminf(mn.z, mw);
                        m = r23.y * hh.w; mw = m * wgt; sum.w += mw; sq.w = fmaf(m, mw, sq.w); mx.w = fmaxf(mx.w, mw); mn.w = fminf(mn.w, mw);
                    }
                }
                if (nacc < degv) {
                    mx.x = fmaxf(mx.x, 0.f); mx.y = fmaxf(mx.y, 0.f); mx.z = fmaxf(mx.z, 0.f); mx.w = fmaxf(mx.w, 0.f);
                    mn.x = fminf(mn.x, 0.f); mn.y = fminf(mn.y, 0.f); mn.z = fminf(mn.z, 0.f); mn.w = fminf(mn.w, 0.f);
                }
                sumF = sum; sqF = sq; mxF = mx; mnF = mn;
            }
        } else {
            act = 1;
            hv = cvt_rv(__ldg(&h16_in[v * DD + d]));
            ull sum01 = pk2(m0.x, m0.y), sum23 = pk2(m0.z, m0.w);
            __half2 sqh01 = __floats2half2_rn(m0.x * m0.x, m0.y * m0.y);
            __half2 sqh23 = __floats2half2_rn(m0.z * m0.z, m0.w * m0.w);
            __half2 mxh01 = __floats2half2_rn(m0.x, m0.y);
            __half2 mxh23 = __floats2half2_rn(m0.z, m0.w);
            __half2 mnh01 = mxh01, mnh23 = mxh23;

            const int nfull = (e_ - p) >> 2;
            if (nfull > 0) {
                int2 ee[4];
#pragma unroll
                for (int j = 0; j < 4; ++j) ee[j] = __ldg(&g_epack[p + j]);
                for (int b = 0; b < nfull; ++b) {
                    uint2 rv[4], hh[4];
#pragma unroll
                    for (int j = 0; j < 4; ++j) {
                        rv[j] = __ldg(&relin[(ee[j].x >> 16) * DD]);
                        hh[j] = ldcg2u(&h16_in[(ee[j].x & 0xFFFF) * DD + d]);
                    }
                    const int wb0 = ee[0].y, wb1 = ee[1].y;
                    const int wb2 = ee[2].y, wb3 = ee[3].y;
                    if (b + 1 < nfull) {
                        const int pn = p + 4 * (b + 1);
#pragma unroll
                        for (int j = 0; j < 4; ++j) ee[j] = __ldg(&g_epack[pn + j]);
                    }
                    __half2 a01, a23, b01, b23, c01, c23, d01, d23;
                    EDGE_CORE(rv[0], hh[0], wb0, a01, a23);
                    EDGE_CORE(rv[1], hh[1], wb1, b01, b23);
                    EDGE_CORE(rv[2], hh[2], wb2, c01, c23);
                    EDGE_CORE(rv[3], hh[3], wb3, d01, d23);
                    const __half2 t01 = __hadd2(__hadd2(a01, b01), __hadd2(c01, d01));
                    const __half2 t23 = __hadd2(__hadd2(a23, b23), __hadd2(c23, d23));
                    sum01 = add2(sum01, h2f2(t01));
                    sum23 = add2(sum23, h2f2(t23));
                }
                p += nfull * 4;
            }
            for (; p < e_; ++p) {
                const int2 e0 = __ldg(&g_epack[p]);
                const uint2 rv0 = __ldg(&relin[(e0.x >> 16) * DD]);
                const uint2 hh0 = ldcg2u(&h16_in[(e0.x & 0xFFFF) * DD + d]);
                __half2 a01, a23;
                EDGE_CORE(rv0, hh0, e0.y, a01, a23);
                sum01 = add2(sum01, h2f2(a01));
                sum23 = add2(sum23, h2f2(a23));
            }
            const float2 s01 = unpk(sum01), s23 = unpk(sum23);
            const float2 q01 = __half22float2(sqh01), q23 = __half22float2(sqh23);
            const float2 x01 = __half22float2(mxh01), x23 = __half22float2(mxh23);
            const float2 n01 = __half22float2(mnh01), n23 = __half22float2(mnh23);
            sumF = make_float4(s01.x, s01.y, s23.x, s23.y);
            sqF  = make_float4(q01.x, q01.y, q23.x, q23.y);
            mxF  = make_float4(x01.x, x01.y, x23.x, x23.y);
            mnF  = make_float4(n01.x, n01.y, n23.x, n23.y);
        }

        if (lane == 0) { s_act[w] = act; s_scl[w] = g_sc[v]; }

        if (act) {
            const float inv = 1.0f / (float)(degv + 1);
            float4 mean, var, sd2;
            mean.x = sumF.x * inv; mean.y = sumF.y * inv; mean.z = sumF.z * inv; mean.w = sumF.w * inv;
            var.x = sqF.x * inv - mean.x * mean.x; var.y = sqF.y * inv - mean.y * mean.y;
            var.z = sqF.z * inv - mean.z * mean.z; var.w = sqF.w * inv - mean.w * mean.w;
            sd2.x = sqrtf(fmaxf(var.x, EPSF)); sd2.y = sqrtf(fmaxf(var.y, EPSF));
            sd2.z = sqrtf(fmaxf(var.z, EPSF)); sd2.w = sqrtf(fmaxf(var.w, EPSF));
            const float2 sc = g_sc[v];
            const int r0 = w * 4;

            float4 hv1;
            hv1.x = __shfl_down_sync(0xffffffffu, hv.x, 1);
            hv1.y = __shfl_down_sync(0xffffffffu, hv.y, 1);
            hv1.z = __shfl_down_sync(0xffffffffu, hv.z, 1);
            hv1.w = __shfl_down_sync(0xffffffffu, hv.w, 1);
            if ((d & 1) == 0) WRITE_PAIRF(d >> 1, hv, hv1);

            float4 f[12];
            const float4 st4[4] = {mean, mxF, mnF, sd2};
#pragma unroll
            for (int si = 0; si < 4; ++si) {
                const float4 fv = st4[si];
                f[si * 3 + 0] = fv;
                f[si * 3 + 1] = make_float4(fv.x * sc.x, fv.y * sc.x, fv.z * sc.x, fv.w * sc.x);
                f[si * 3 + 2] = make_float4(fv.x * sc.y, fv.y * sc.y, fv.z * sc.y, fv.w * sc.y);
            }
            const int pb = 16 + 6 * d;
#pragma unroll
            for (int pi = 0; pi < 6; ++pi)
                WRITE_PAIRF(pb + pi, f[2 * pi], f[2 * pi + 1]);
        }
    }
    __syncthreads();

    const int anyact = s_act[0] | s_act[1] | s_act[2] | s_act[3];

    // ---- GEMM via mma.sync fp16 A + 2-term fp16 W (2 mma / k-step) ----
    float d0 = 0.f, d1 = 0.f, d2 = 0.f, d3 = 0.f;
    const int c = lane & 3, g = lane >> 2;
    if (anyact) {
        const uint4* Wp = g_Wmma + (size_t)layer * NSTEP * 128 + (w * 32 + lane);
#pragma unroll
        for (int s = 0; s < NSTEP; ++s) {
            const uint4 wv = __ldg(&Wp[(size_t)s * 128]);
            const int pA = s * 8 + c, pB = s * 8 + 4 + c;
            const uint32_t a0 = catF[pA][g], a1 = catF[pA][g + 8];
            const uint32_t a2 = catF[pB][g], a3 = catF[pB][g + 8];
            mma16816h(d0, d1, d2, d3, a0, a1, a2, a3, wv.x, wv.y);   // W hi
            mma16816h(d0, d1, d2, d3, a0, a1, a2, a3, wv.z, wv.w);   // W lo
        }
    }
    __syncthreads();    // all warps done READING catF before sD overwrites it
    if (anyact) {
        const int j0 = 8 * w + 2 * c;
        sD[g * 33 + j0] = d0;       sD[g * 33 + j0 + 1] = d1;
        sD[(g + 8) * 33 + j0] = d2; sD[(g + 8) * 33 + j0 + 1] = d3;
    }
    __syncthreads();

    // ---- epilogue: fp16 hidden only ----
    {
        const float bias = lin_b[layer * DD + lane];
        float4 o;
        if (s_act[w]) {
            o = make_float4(fmaxf(sD[(w * 4 + 0) * 33 + lane] + bias, 0.0f),
                            fmaxf(sD[(w * 4 + 1) * 33 + lane] + bias, 0.0f),
                            fmaxf(sD[(w * 4 + 2) * 33 + lane] + bias, 0.0f),
                            fmaxf(sD[(w * 4 + 3) * 33 + lane] + bias, 0.0f));
        } else {
            const float sd = sqrtf(EPSF);
            const float2 sc = s_scl[w];
            const float c2 = g_csum[lane] + sc.x * g_csum[DD + lane] + sc.y * g_csum[2 * DD + lane];
            const float val = fmaxf(bias + sd * c2, 0.0f);
            o = make_float4(val, val, val, val);
        }
        const __half2 o01 = __floats2half2_rn(o.x, o.y);
        const __half2 o23 = __floats2half2_rn(o.z, o.w);
        uint2 ho;
        ho.x = h2u(o01);
        ho.y = h2u(o23);
        h16_out[v * DD + lane] = ho;
    }
}

// ---------------- final MLP scoring via mma (block = 32 nodes / iter) ----------------
__global__ void __launch_bounds__(256) mlp_kernel(
    const uint2* __restrict__ hid16,
    const float* __restrict__ b1,
    const float* __restrict__ W2, const float* __restrict__ b2,
    float* __restrict__ out)
{
    __shared__ uint32_t fA[32][132];   // fp16x2 [k-pair][row 0..127] 16.5KB
    __shared__ float b1s[64];
    __shared__ float W2s[64];

    const int t = threadIdx.x, w = t >> 5, lane = t & 31;
    const int c = lane & 3, g = lane >> 2;
    if (t < 64) { b1s[t] = b1[t]; W2s[t] = W2[t]; }

    for (int it = 0; it < MLP_IT2; ++it) {
        const int vbase = (blockIdx.x * MLP_IT2 + it) * 32;
        __syncthreads();
        {
            const int r = t >> 1, half = t & 1;
            const int v = vbase + (r >> 2), b = r & 3;
            if (half == 0) {
                const uint2* hp = hid16 + (size_t)v * DD;
#pragma unroll
                for (int kp = 0; kp < 16; ++kp) {
                    float x0 = 0.f, x1 = 0.f;
                    if (v < NN) {
                        x0 = h16get(__ldg(&hp[2 * kp]), b);
                        x1 = h16get(__ldg(&hp[2 * kp + 1]), b);
                    }
                    fA[kp][r] = pkh2(x0, x1);
                }
            } else {
#pragma unroll
                for (int kp = 0; kp < 16; ++kp) {
                    const float4 q0 = g_qT[2 * kp];
                    const float4 q1 = g_qT[2 * kp + 1];
                    const float x0 = (b == 0) ? q0.x : (b == 1) ? q0.y : (b == 2) ? q0.z : q0.w;
                    const float x1 = (b == 0) ? q1.x : (b == 1) ? q1.y : (b == 2) ? q1.z : q1.w;
                    fA[16 + kp][r] = pkh2(x0, x1);
                }
            }
        }
        __syncthreads();

        const int base = w * 16;
        float sLo = 0.f, sHi = 0.f;
#pragma unroll
        for (int j = 0; j < 8; ++j) {
            float d0 = 0.f, d1 = 0.f, d2 = 0.f, d3 = 0.f;
#pragma unroll
            for (int s = 0; s < 4; ++s) {
                const uint4 wv = __ldg(&g_W1mma[(s * 8 + j) * 32 + lane]);
                const int pA = s * 8 + c, pB = pA + 4;
                const uint32_t a0 = fA[pA][base + g], a1 = fA[pA][base + g + 8];
                const uint32_t a2 = fA[pB][base + g], a3 = fA[pB][base + g + 8];
                mma16816h(d0, d1, d2, d3, a0, a1, a2, a3, wv.x, wv.y);
                mma16816h(d0, d1, d2, d3, a0, a1, a2, a3, wv.z, wv.w);
            }
            const int n0 = 8 * j + 2 * c, n1 = n0 + 1;
            sLo += fmaxf(d0 + b1s[n0], 0.0f) * W2s[n0] + fmaxf(d1 + b1s[n1], 0.0f) * W2s[n1];
            sHi += fmaxf(d2 + b1s[n0], 0.0f) * W2s[n0] + fmaxf(d3 + b1s[n1], 0.0f) * W2s[n1];
        }
        sLo += __shfl_xor_sync(0xffffffffu, sLo, 1);
        sLo += __shfl_xor_sync(0xffffffffu, sLo, 2);
        sHi += __shfl_xor_sync(0xffffffffu, sHi, 1);
        sHi += __shfl_xor_sync(0xffffffffu, sHi, 2);
        if (c == 0) {
            const float bias2 = __ldg(&b2[0]);
            const int R0 = base + g;
            const int v0 = vbase + (R0 >> 2), b0 = R0 & 3;
            if (v0 < NN) out[b0 * NN + v0] = sLo + bias2;
            const int R1 = base + g + 8;
            const int v1 = vbase + (R1 >> 2), bb1 = R1 & 3;
            if (v1 < NN) out[bb1 * NN + v1] = sHi + bias2;
        }
    }
}

// ---------------- launch ----------------
extern "C" void kernel_launch(void* const* d_in, const int* in_sizes, int n_in,
                              void* d_out, int out_size) {
    const int*   node_in     = (const int*)  d_in[0];
    const int*   node_out    = (const int*)  d_in[1];
    const int*   relation    = (const int*)  d_in[2];
    const float* edge_weight = (const float*)d_in[3];
    const int*   h_index     = (const int*)  d_in[4];
    const int*   r_index     = (const int*)  d_in[5];
    const float* query_embed = (const float*)d_in[6];
    const float* rel_W  = (const float*)d_in[7];
    const float* rel_b  = (const float*)d_in[8];
    const float* lin_W  = (const float*)d_in[9];
    const float* lin_b  = (const float*)d_in[10];
    const float* mlp_W1 = (const float*)d_in[11];
    const float* mlp_b1 = (const float*)d_in[12];
    const float* mlp_W2 = (const float*)d_in[13];
    const float* mlp_b2 = (const float*)d_in[14];
    float* out = (float*)d_out;

    uint2 *h16A, *h16B;
    cudaGetSymbolAddress((void**)&h16A, g_h16A);
    cudaGetSymbolAddress((void**)&h16B, g_h16B);

    setup_kernel<<<SB_TOTAL, 128>>>(h_index, r_index, query_embed,
                                    lin_W, rel_W, rel_b, mlp_W1);  // 0
    hist_kernel<<<(NE + 255) / 256, 256>>>(node_out, edge_weight); // 1
    scan_kernel<<<SCAN_B, 1024>>>();                               // 2
    scatter_kernel<<<(NE + 255) / 256, 256>>>(node_in, node_out, relation,
                                              edge_weight, h_index); // 3

    const uint2* h16in = h16A;       // unused at layer 0
    uint2* h16outs[4] = {h16A, h16B, h16A, h16B};
    for (int l = 0; l < NL; ++l) {
        conv_kernel<<<NN / 4, 128>>>(lin_b, h16in, h16outs[l], h_index, l); // 4..7
        h16in = h16outs[l];
    }
    mlp_kernel<<<(NN + 32 * MLP_IT2 - 1) / (32 * MLP_IT2), 256>>>(
        h16in, mlp_b1, mlp_W2, mlp_b2, out);                       // 8
}